// round 8
// baseline (speedup 1.0000x reference)
#include <cuda_runtime.h>
#include <cstdint>
#include <math.h>

#define B_     4
#define NCH    32
#define T_FULL 65536
#define T_IN   8192
#define L_     256
#define HOP_   256
#define H_     64
#define KC_    24576

// ---- scratch (device globals; no allocation allowed) ----
__device__ float g_H [B_*NCH*T_FULL];
__device__ float g_C [B_*NCH*T_FULL];
__device__ float g_F0[B_*H_*L_];
__device__ float g_KT[B_*L_*KC_];       // predicted kernels [n=b*L+l][kc]
__device__ float g_BS[B_*256*L_];       // predicted biases [b][bc][l]

__device__ __forceinline__ float lrelu(float x){ return x >= 0.f ? x : 0.2f*x; }

// ---- packed f32x2 helpers ----
__device__ __forceinline__ uint64_t pack2f(float lo, float hi){
    uint64_t r; asm("mov.b64 %0, {%1, %2};" : "=l"(r) : "f"(lo), "f"(hi)); return r;
}
__device__ __forceinline__ uint64_t bcast2f(float x){ return pack2f(x, x); }
__device__ __forceinline__ void fma2(uint64_t& d, uint64_t a, uint64_t b){
    asm("fma.rn.f32x2 %0, %1, %2, %0;" : "+l"(d) : "l"(a), "l"(b));
}
__device__ __forceinline__ float2 unpack2f(uint64_t v){
    float2 r; asm("mov.b64 {%0, %1}, %2;" : "=f"(r.x), "=f"(r.y) : "l"(v)); return r;
}

// ============================================================
// K1: conv_transpose1d  (stride 8, K=16, pad 4)
// ============================================================
__global__ void k_convT(const float* __restrict__ x, const float* __restrict__ w,
                        const float* __restrict__ bias){
    int b  = blockIdx.y;
    int t0 = blockIdx.x * 256;
    int tid = threadIdx.x;
    int r = tid & 7, o = tid >> 3;
    __shared__ float xs[NCH*36];
    const float* xb = x + b*NCH*T_IN;
    int jbase = t0/8 - 1;
    for (int idx = tid; idx < NCH*34; idx += 256){
        int c = idx / 34, p = idx % 34;
        int j = jbase + p;
        xs[c*36 + p] = (j >= 0 && j < T_IN) ? xb[c*T_IN + j] : 0.f;
    }
    __syncthreads();
    float acc[32];
    float bv = bias[o];
    #pragma unroll
    for (int s = 0; s < 32; s++) acc[s] = bv;
    int off = (r + 4) & 7;
    int e   = (off >= 4) ? 1 : 0;
    for (int i = 0; i < NCH; i++){
        float w1 = w[(i*32 + o)*16 + r];
        float w2 = w[(i*32 + o)*16 + r + 8];
        const float* xr = &xs[i*36 + e];
        float vp = xr[0];
        #pragma unroll
        for (int s = 0; s < 32; s++){
            float v = xr[s + 1];
            acc[s] += w1*v + w2*vp;
            vp = v;
        }
    }
    float* out = &g_H[(b*NCH + o)*T_FULL];
    #pragma unroll
    for (int s = 0; s < 32; s++) out[t0 + off + 8*s] = acc[s];
}

// ============================================================
// K2: FUSED kernel predictor (spec conv + 3 residual blocks).
// ============================================================
#define PRED_SMEM ((100*52 + 64*52 + 64*52 + 16000)*4)

__device__ __forceinline__ void pred_conv3(
    const float* src, float* dst, const float* rsd, float* wbuf,
    const float* __restrict__ wsrc, const float* __restrict__ bsrc,
    int plo, int phi, int l0, int hq, int pb, int tid){
    __syncthreads();
    for (int idx = tid; idx < 64*192; idx += 256){
        int h = idx/192, ck = idx%192;
        wbuf[ck*64 + h] = wsrc[h*192 + ck];
    }
    __syncthreads();
    uint64_t acc[2][3];
    #pragma unroll
    for (int m = 0; m < 2; m++){
        uint64_t bp = pack2f(bsrc[hq*4 + 2*m], bsrc[hq*4 + 2*m + 1]);
        acc[m][0]=bp; acc[m][1]=bp; acc[m][2]=bp;
    }
    for (int c = 0; c < 64; c++){
        float xv[5];
        #pragma unroll
        for (int m = 0; m < 5; m++) xv[m] = src[c*52 + pb + 1 + m];
        #pragma unroll
        for (int k = 0; k < 3; k++){
            ulonglong2 wp = *(const ulonglong2*)&wbuf[(c*3 + k)*64 + hq*4];
            #pragma unroll
            for (int j = 0; j < 3; j++){
                uint64_t xb = bcast2f(xv[j + k]);
                fma2(acc[0][j], wp.x, xb);
                fma2(acc[1][j], wp.y, xb);
            }
        }
    }
    #pragma unroll
    for (int m = 0; m < 2; m++)
    #pragma unroll
    for (int j = 0; j < 3; j++){
        int p = pb + j;
        if (p >= plo && p <= phi){
            int gl = l0 - 8 + p;
            bool ok = (gl >= 0 && gl < L_);
            float2 u = unpack2f(acc[m][j]);
            int ch0 = hq*4 + 2*m;
            float v0 = lrelu(u.x), v1 = lrelu(u.y);
            if (rsd){ v0 += rsd[ch0*52 + p + 2]; v1 += rsd[(ch0+1)*52 + p + 2]; }
            dst[ch0*52 + p + 2]     = ok ? v0 : 0.f;
            dst[(ch0+1)*52 + p + 2] = ok ? v1 : 0.f;
        }
    }
}

__global__ void __launch_bounds__(256)
k_pred(const float* __restrict__ spec,
       const float* __restrict__ kp_w, const float* __restrict__ kp_b,
       const float* __restrict__ rb_w1, const float* __restrict__ rb_b1,
       const float* __restrict__ rb_w2, const float* __restrict__ rb_b2){
    extern __shared__ float sm[];
    float* sspec = sm;
    float* bufA  = sm + 100*52;
    float* bufB  = bufA + 64*52;
    float* wbuf  = bufB + 64*52;
    int b = blockIdx.x, ls = blockIdx.y;
    int l0 = ls*32;
    int tid = threadIdx.x;
    int hq = tid >> 4;
    int pb = (tid & 15) * 3;

    const float* sp = spec + b*100*L_;
    for (int idx = tid; idx < 100*52; idx += 256){
        int c = idx/52, q = idx%52;
        int gl = l0 - 10 + q;
        sspec[c*52 + q] = (gl >= 0 && gl < L_) ? sp[c*L_ + gl] : 0.f;
    }
    uint64_t acc[2][3];
    #pragma unroll
    for (int m = 0; m < 2; m++){
        uint64_t bp = pack2f(kp_b[hq*4 + 2*m], kp_b[hq*4 + 2*m + 1]);
        acc[m][0]=bp; acc[m][1]=bp; acc[m][2]=bp;
    }
    for (int chunk = 0; chunk < 2; chunk++){
        __syncthreads();
        for (int idx = tid; idx < 16000; idx += 256){
            int h = idx/250, ck = idx%250;
            wbuf[ck*64 + h] = kp_w[h*500 + chunk*250 + ck];
        }
        __syncthreads();
        for (int c2 = 0; c2 < 50; c2++){
            int c = chunk*50 + c2;
            float xv[7];
            #pragma unroll
            for (int m = 0; m < 7; m++) xv[m] = sspec[c*52 + pb + m];
            #pragma unroll
            for (int k = 0; k < 5; k++){
                ulonglong2 wp = *(const ulonglong2*)&wbuf[(c2*5 + k)*64 + hq*4];
                #pragma unroll
                for (int j = 0; j < 3; j++){
                    uint64_t xb = bcast2f(xv[j + k]);
                    fma2(acc[0][j], wp.x, xb);
                    fma2(acc[1][j], wp.y, xb);
                }
            }
        }
    }
    #pragma unroll
    for (int m = 0; m < 2; m++)
    #pragma unroll
    for (int j = 0; j < 3; j++){
        int p = pb + j;
        if (p >= 2 && p <= 45){
            int gl = l0 - 8 + p;
            bool ok = (gl >= 0 && gl < L_);
            float2 u = unpack2f(acc[m][j]);
            int ch0 = hq*4 + 2*m;
            bufA[ch0*52 + p + 2]     = ok ? u.x : 0.f;
            bufA[(ch0+1)*52 + p + 2] = ok ? u.y : 0.f;
        }
    }
    #pragma unroll 1
    for (int i = 0; i < 3; i++){
        pred_conv3(bufA, bufB, nullptr, wbuf, rb_w1 + i*12288, rb_b1 + i*64,
                   3+2*i, 44-2*i, l0, hq, pb, tid);
        pred_conv3(bufB, bufA, bufA,    wbuf, rb_w2 + i*12288, rb_b2 + i*64,
                   4+2*i, 43-2*i, l0, hq, pb, tid);
    }
    __syncthreads();
    #pragma unroll
    for (int m = 0; m < 2; m++)
    #pragma unroll
    for (int j = 0; j < 3; j++){
        int p = pb + j;
        if (p >= 8 && p <= 39){
            int l = l0 - 8 + p;
            int ch0 = hq*4 + 2*m;
            g_F0[(b*H_ + ch0    )*L_ + l] = bufA[ch0*52 + p + 2];
            g_F0[(b*H_ + ch0 + 1)*L_ + l] = bufA[(ch0+1)*52 + p + 2];
        }
    }
}

// ============================================================
// K5: kern conv as GEMM (f32x2):  C[n][kc] = sum_r A[kc][r]*X[r][n]
// ============================================================
__global__ void __launch_bounds__(256)
k_kern_gemm(const float* __restrict__ A, const float* __restrict__ Ab){
    int kc0 = blockIdx.x * 128;
    int n0  = blockIdx.y * 128;
    int b   = n0 / L_;
    int l0w = n0 % L_;
    int tid = threadIdx.x;
    int ty = tid / 16, tx = tid % 16;
    __shared__ __align__(16) float As[16][128];
    __shared__ __align__(16) float Xs[16][128];
    const float* F = &g_F0[b*H_*L_];

    uint64_t acc2[4][8];
    #pragma unroll
    for (int m = 0; m < 4; m++){
        uint64_t bp = pack2f(Ab[kc0 + ty*8 + 2*m], Ab[kc0 + ty*8 + 2*m + 1]);
        #pragma unroll
        for (int j = 0; j < 8; j++) acc2[m][j] = bp;
    }
    int arow = tid >> 1, ac0 = (tid & 1) * 8;
    int xrr = tid >> 4, xl0 = (tid & 15) * 8;
    for (int bk = 0; bk < 12; bk++){
        int r0 = bk*16;
        float4 v0 = *(const float4*)&A[(kc0 + arow)*192 + r0 + ac0];
        float4 v1 = *(const float4*)&A[(kc0 + arow)*192 + r0 + ac0 + 4];
        As[ac0+0][arow] = v0.x; As[ac0+1][arow] = v0.y;
        As[ac0+2][arow] = v0.z; As[ac0+3][arow] = v0.w;
        As[ac0+4][arow] = v1.x; As[ac0+5][arow] = v1.y;
        As[ac0+6][arow] = v1.z; As[ac0+7][arow] = v1.w;
        {
            int r = r0 + xrr;
            int hh = r/3, k = r%3;
            #pragma unroll
            for (int q = 0; q < 8; q++){
                int t = l0w + xl0 + q + k - 1;
                Xs[xrr][xl0+q] = (t >= 0 && t < L_) ? F[hh*L_ + t] : 0.f;
            }
        }
        __syncthreads();
        #pragma unroll
        for (int kk = 0; kk < 16; kk++){
            ulonglong2 aA = *(const ulonglong2*)&As[kk][ty*8];
            ulonglong2 aB = *(const ulonglong2*)&As[kk][ty*8 + 4];
            uint64_t a2[4] = {aA.x, aA.y, aB.x, aB.y};
            float4 x0 = *(const float4*)&Xs[kk][tx*8];
            float4 x1 = *(const float4*)&Xs[kk][tx*8 + 4];
            uint64_t xb[8];
            xb[0] = bcast2f(x0.x); xb[1] = bcast2f(x0.y);
            xb[2] = bcast2f(x0.z); xb[3] = bcast2f(x0.w);
            xb[4] = bcast2f(x1.x); xb[5] = bcast2f(x1.y);
            xb[6] = bcast2f(x1.z); xb[7] = bcast2f(x1.w);
            #pragma unroll
            for (int j = 0; j < 8; j++)
                #pragma unroll
                for (int m = 0; m < 4; m++)
                    fma2(acc2[m][j], a2[m], xb[j]);
        }
        __syncthreads();
    }
    #pragma unroll
    for (int j = 0; j < 8; j++){
        int n = n0 + tx*8 + j;
        #pragma unroll
        for (int m = 0; m < 4; m++){
            float2 p = unpack2f(acc2[m][j]);
            *(float2*)&g_KT[n*KC_ + kc0 + ty*8 + 2*m] = p;
        }
    }
}

// ============================================================
// K6: bias conv (64->256, K=3, pad 1) -> g_BS[b][bc][l]
// ============================================================
__global__ void k_biasconv(const float* __restrict__ w, const float* __restrict__ bias){
    int b = blockIdx.x, lt = blockIdx.y, bct = blockIdx.z;
    int tid = threadIdx.x;
    __shared__ float xs[64][36];
    __shared__ __align__(16) float ws[192][64];
    const float* in = &g_F0[b*H_*L_];
    int l0 = lt*32, bc0 = bct*64;
    for (int idx = tid; idx < 64*34; idx += 256){
        int c = idx / 34, p = idx % 34;
        int t = l0 - 1 + p;
        xs[c][p] = (t >= 0 && t < L_) ? in[c*L_ + t] : 0.f;
    }
    for (int idx = tid; idx < 64*192; idx += 256){
        int h = idx / 192, ck = idx % 192;
        ws[ck][h] = w[(bc0 + h)*192 + ck];
    }
    __syncthreads();
    int hq = tid >> 5, li = tid & 31;
    uint64_t acc2[4];
    #pragma unroll
    for (int m = 0; m < 4; m++)
        acc2[m] = pack2f(bias[bc0 + hq*8 + 2*m], bias[bc0 + hq*8 + 2*m + 1]);
    for (int c = 0; c < 64; c++){
        #pragma unroll
        for (int k = 0; k < 3; k++){
            uint64_t xb = bcast2f(xs[c][li + k]);
            const float* wr = &ws[c*3 + k][hq*8];
            ulonglong2 wA = *(const ulonglong2*)wr;
            ulonglong2 wB = *(const ulonglong2*)(wr + 4);
            fma2(acc2[0], wA.x, xb);
            fma2(acc2[1], wA.y, xb);
            fma2(acc2[2], wB.x, xb);
            fma2(acc2[3], wB.y, xb);
        }
    }
    int l = l0 + li;
    #pragma unroll
    for (int m = 0; m < 4; m++){
        float2 p = unpack2f(acc2[m]);
        g_BS[(b*256 + bc0 + hq*8 + 2*m    )*L_ + l] = p.x;
        g_BS[(b*256 + bc0 + hq*8 + 2*m + 1)*L_ + l] = p.y;
    }
}

// ============================================================
// K7: fused lrelu -> dilated conv (32->32,K=3,pad D) -> lrelu into g_C
// 3 dilation-shifted smem copies -> all x loads are aligned float4,
// lane-contiguous. 256-sample tile, thread = 8 ch x 4 samples.
// ============================================================
#define DCONV_SMEM ((3*32*256 + 3072)*4)
template<int D>
__global__ void __launch_bounds__(256)
k_dconv(const float* __restrict__ w, const float* __restrict__ bias){
    extern __shared__ float sm[];
    float* xs = sm;            // [k][c][s]: k*8192 + c*256 + s
    float* ws = sm + 3*8192;   // [k][i][o]
    int b  = blockIdx.y;
    int t0 = blockIdx.x * 256;
    int tid = threadIdx.x;
    const float* Hb = &g_H[b*NCH*T_FULL];
    #pragma unroll
    for (int k = 0; k < 3; k++){
        int sh = (k - 1)*D;
        for (int idx = tid; idx < 32*256; idx += 256){
            int t = t0 + (idx & 255) + sh;
            xs[k*8192 + idx] = (t >= 0 && t < T_FULL)
                               ? lrelu(Hb[(idx >> 8)*T_FULL + t]) : 0.f;
        }
    }
    for (int idx = tid; idx < 3072; idx += 256){
        int o = idx / 96, rem = idx % 96;
        int i = rem / 3, k = rem % 3;
        ws[k*1024 + i*32 + o] = w[idx];
    }
    __syncthreads();
    int wgrp = tid >> 5;
    int o0 = (wgrp & 3) * 8;
    int s0 = (wgrp >> 2) * 128 + (tid & 31) * 4;
    uint64_t acc[4][4];
    #pragma unroll
    for (int m = 0; m < 4; m++){
        uint64_t bp = pack2f(bias[o0 + 2*m], bias[o0 + 2*m + 1]);
        #pragma unroll
        for (int j = 0; j < 4; j++) acc[m][j] = bp;
    }
    for (int i = 0; i < NCH; i++){
        #pragma unroll
        for (int k = 0; k < 3; k++){
            float4 xv = *(const float4*)&xs[k*8192 + i*256 + s0];
            uint64_t xb[4] = {bcast2f(xv.x), bcast2f(xv.y), bcast2f(xv.z), bcast2f(xv.w)};
            ulonglong2 wA = *(const ulonglong2*)&ws[k*1024 + i*32 + o0];
            ulonglong2 wB = *(const ulonglong2*)&ws[k*1024 + i*32 + o0 + 4];
            #pragma unroll
            for (int j = 0; j < 4; j++){
                fma2(acc[0][j], wA.x, xb[j]);
                fma2(acc[1][j], wA.y, xb[j]);
                fma2(acc[2][j], wB.x, xb[j]);
                fma2(acc[3][j], wB.y, xb[j]);
            }
        }
    }
    float* Cb = &g_C[b*NCH*T_FULL];
    #pragma unroll
    for (int cc = 0; cc < 8; cc++){
        float tmp[4];
        #pragma unroll
        for (int j = 0; j < 4; j++){
            float2 u = unpack2f(acc[cc>>1][j]);
            tmp[j] = lrelu((cc & 1) ? u.y : u.x);
        }
        *(float4*)&Cb[(o0 + cc)*T_FULL + t0 + s0] =
            make_float4(tmp[0], tmp[1], tmp[2], tmp[3]);
    }
}

// ============================================================
// K8: location-variable conv + bias + gating + residual (fused)
// Half-segments (128 samples), thread = 4 ch x 4 contiguous samples.
// ============================================================
#define LVC_SMEM ((32*136 + 6144)*4)
__global__ void __launch_bounds__(256)
k_lvc(int layer, float* __restrict__ outp){
    extern __shared__ float sm[];
    float* xs  = sm;            // stride 136 (130 used)
    float* ksh = sm + 32*136;   // [k][c][o]
    int b = blockIdx.z, l = blockIdx.x, h0 = blockIdx.y * 128;
    int tid = threadIdx.x;
    const float* Cb  = &g_C[b*NCH*T_FULL];
    const float* KTb = &g_KT[(b*L_ + l)*KC_ + layer*6144];
    int tseg = l*HOP_;
    for (int idx = tid; idx < 32*130; idx += 256){
        int c = idx / 130, p = idx % 130;
        int t = tseg + h0 - 1 + p;
        xs[c*136 + p] = (t >= 0 && t < T_FULL) ? Cb[c*T_FULL + t] : 0.f;
    }
    const float4* K4 = (const float4*)KTb;
    for (int i4 = tid; i4 < 1536; i4 += 256){
        float4 v = K4[i4];
        float vv[4] = {v.x, v.y, v.z, v.w};
        int base = i4*4;
        #pragma unroll
        for (int e = 0; e < 4; e++){
            int idx = base + e;
            int c = idx / 192, rem = idx % 192;
            int o = rem / 3, k = rem % 3;
            ksh[k*2048 + c*64 + o] = vv[e];
        }
    }
    __syncthreads();
    int o0 = (tid >> 5) * 4;     // 8 warps x 4 channels
    int s0 = (tid & 31) * 4;     // 32 lanes x 4 contiguous samples
    const float* Bb = &g_BS[(b*256 + layer*64)*L_];
    uint64_t accL[2][4], accH[2][4];
    #pragma unroll
    for (int m = 0; m < 2; m++){
        uint64_t bl = pack2f(Bb[(o0 + 2*m)*L_ + l],      Bb[(o0 + 2*m + 1)*L_ + l]);
        uint64_t bh = pack2f(Bb[(o0 + 2*m + 32)*L_ + l], Bb[(o0 + 2*m + 33)*L_ + l]);
        #pragma unroll
        for (int j = 0; j < 4; j++){ accL[m][j] = bl; accH[m][j] = bh; }
    }
    for (int c = 0; c < NCH; c++){
        const float* xr = &xs[c*136 + s0];
        float4 xa = *(const float4*)xr;
        float2 xc = *(const float2*)(xr + 4);
        uint64_t xb[6];
        xb[0] = bcast2f(xa.x); xb[1] = bcast2f(xa.y); xb[2] = bcast2f(xa.z);
        xb[3] = bcast2f(xa.w); xb[4] = bcast2f(xc.x); xb[5] = bcast2f(xc.y);
        #pragma unroll
        for (int k = 0; k < 3; k++){
            ulonglong2 wl = *(const ulonglong2*)&ksh[k*2048 + c*64 + o0];
            ulonglong2 wh = *(const ulonglong2*)&ksh[k*2048 + c*64 + o0 + 32];
            #pragma unroll
            for (int j = 0; j < 4; j++){
                uint64_t x = xb[j + k];
                fma2(accL[0][j], wl.x, x);
                fma2(accL[1][j], wl.y, x);
                fma2(accH[0][j], wh.x, x);
                fma2(accH[1][j], wh.y, x);
            }
        }
    }
    float* Hb = &g_H[b*NCH*T_FULL];
    float* Ob = outp ? &outp[b*NCH*T_FULL] : Hb;
    int tb = tseg + h0 + s0;
    #pragma unroll
    for (int cc = 0; cc < 4; cc++){
        int oc = o0 + cc;
        float4 r = *(const float4*)&Hb[oc*T_FULL + tb];
        float rr[4] = {r.x, r.y, r.z, r.w};
        float tmp[4];
        #pragma unroll
        for (int j = 0; j < 4; j++){
            float2 uL = unpack2f(accL[cc>>1][j]);
            float2 uH = unpack2f(accH[cc>>1][j]);
            float aL = (cc & 1) ? uL.y : uL.x;
            float aH = (cc & 1) ? uH.y : uH.x;
            float sg = 1.f / (1.f + __expf(-aL));
            float th = tanhf(aH);
            tmp[j] = sg*th + rr[j];
        }
        *(float4*)&Ob[oc*T_FULL + tb] = make_float4(tmp[0], tmp[1], tmp[2], tmp[3]);
    }
}

// ============================================================
extern "C" void kernel_launch(void* const* d_in, const int* in_sizes, int n_in,
                              void* d_out, int out_size){
    const float* hidden  = (const float*)d_in[0];
    const float* spec    = (const float*)d_in[1];
    const float* convt_w = (const float*)d_in[2];
    const float* convt_b = (const float*)d_in[3];
    const float* kp_in_w = (const float*)d_in[4];
    const float* kp_in_b = (const float*)d_in[5];
    const float* rb_w1   = (const float*)d_in[6];
    const float* rb_b1   = (const float*)d_in[7];
    const float* rb_w2   = (const float*)d_in[8];
    const float* rb_b2   = (const float*)d_in[9];
    const float* kern_w  = (const float*)d_in[10];
    const float* kern_b  = (const float*)d_in[11];
    const float* bias_w  = (const float*)d_in[12];
    const float* bias_b  = (const float*)d_in[13];
    const float* lvc_w   = (const float*)d_in[14];
    const float* lvc_b   = (const float*)d_in[15];

    cudaFuncSetAttribute(k_pred, cudaFuncAttributeMaxDynamicSharedMemorySize, PRED_SMEM);
    cudaFuncSetAttribute(k_lvc,  cudaFuncAttributeMaxDynamicSharedMemorySize, LVC_SMEM);
    cudaFuncSetAttribute(k_dconv<1>,  cudaFuncAttributeMaxDynamicSharedMemorySize, DCONV_SMEM);
    cudaFuncSetAttribute(k_dconv<3>,  cudaFuncAttributeMaxDynamicSharedMemorySize, DCONV_SMEM);
    cudaFuncSetAttribute(k_dconv<9>,  cudaFuncAttributeMaxDynamicSharedMemorySize, DCONV_SMEM);
    cudaFuncSetAttribute(k_dconv<27>, cudaFuncAttributeMaxDynamicSharedMemorySize, DCONV_SMEM);

    k_convT<<<dim3(256, B_), 256>>>(hidden, convt_w, convt_b);
    k_pred<<<dim3(B_, 8), 256, PRED_SMEM>>>(spec, kp_in_w, kp_in_b,
                                            rb_w1, rb_b1, rb_w2, rb_b2);
    k_kern_gemm<<<dim3(KC_/128, (B_*L_)/128), 256>>>(kern_w, kern_b);
    k_biasconv<<<dim3(B_, 8, 4), 256>>>(bias_w, bias_b);

    for (int i = 0; i < 4; i++){
        const float* wi = lvc_w + i*3072;
        const float* bi = lvc_b + i*32;
        dim3 dg(T_FULL/256, B_);
        if      (i == 0) k_dconv<1> <<<dg, 256, DCONV_SMEM>>>(wi, bi);
        else if (i == 1) k_dconv<3> <<<dg, 256, DCONV_SMEM>>>(wi, bi);
        else if (i == 2) k_dconv<9> <<<dg, 256, DCONV_SMEM>>>(wi, bi);
        else             k_dconv<27><<<dg, 256, DCONV_SMEM>>>(wi, bi);
        k_lvc<<<dim3(L_, 2, B_), 256, LVC_SMEM>>>(i, (i == 3) ? (float*)d_out : nullptr);
    }
}

// round 10
// speedup vs baseline: 1.0721x; 1.0721x over previous
#include <cuda_runtime.h>
#include <cstdint>
#include <math.h>

#define B_     4
#define NCH    32
#define T_FULL 65536
#define T_IN   8192
#define L_     256
#define HOP_   256
#define H_     64
#define KC_    24576

// ---- scratch (device globals; no allocation allowed) ----
__device__ float g_H [B_*NCH*T_FULL];
__device__ float g_C [B_*NCH*T_FULL];
__device__ float g_F0[B_*H_*L_];
__device__ float g_KT[B_*L_*KC_];       // predicted kernels [n=b*L+l][kc]
__device__ float g_BS[B_*256*L_];       // predicted biases [b][bc][l]

__device__ __forceinline__ float lrelu(float x){ return x >= 0.f ? x : 0.2f*x; }

// ---- packed f32x2 helpers ----
__device__ __forceinline__ uint64_t pack2f(float lo, float hi){
    uint64_t r; asm("mov.b64 %0, {%1, %2};" : "=l"(r) : "f"(lo), "f"(hi)); return r;
}
__device__ __forceinline__ uint64_t bcast2f(float x){ return pack2f(x, x); }
__device__ __forceinline__ void fma2(uint64_t& d, uint64_t a, uint64_t b){
    asm("fma.rn.f32x2 %0, %1, %2, %0;" : "+l"(d) : "l"(a), "l"(b));
}
__device__ __forceinline__ float2 unpack2f(uint64_t v){
    float2 r; asm("mov.b64 {%0, %1}, %2;" : "=f"(r.x), "=f"(r.y) : "l"(v)); return r;
}

// ============================================================
// K1: conv_transpose1d  (stride 8, K=16, pad 4)
// ============================================================
__global__ void k_convT(const float* __restrict__ x, const float* __restrict__ w,
                        const float* __restrict__ bias){
    int b  = blockIdx.y;
    int t0 = blockIdx.x * 256;
    int tid = threadIdx.x;
    int r = tid & 7, o = tid >> 3;
    __shared__ float xs[NCH*36];
    const float* xb = x + b*NCH*T_IN;
    int jbase = t0/8 - 1;
    for (int idx = tid; idx < NCH*34; idx += 256){
        int c = idx / 34, p = idx % 34;
        int j = jbase + p;
        xs[c*36 + p] = (j >= 0 && j < T_IN) ? xb[c*T_IN + j] : 0.f;
    }
    __syncthreads();
    float acc[32];
    float bv = bias[o];
    #pragma unroll
    for (int s = 0; s < 32; s++) acc[s] = bv;
    int off = (r + 4) & 7;
    int e   = (off >= 4) ? 1 : 0;
    for (int i = 0; i < NCH; i++){
        float w1 = w[(i*32 + o)*16 + r];
        float w2 = w[(i*32 + o)*16 + r + 8];
        const float* xr = &xs[i*36 + e];
        float vp = xr[0];
        #pragma unroll
        for (int s = 0; s < 32; s++){
            float v = xr[s + 1];
            acc[s] += w1*v + w2*vp;
            vp = v;
        }
    }
    float* out = &g_H[(b*NCH + o)*T_FULL];
    #pragma unroll
    for (int s = 0; s < 32; s++) out[t0 + off + 8*s] = acc[s];
}

// ============================================================
// K2: FUSED kernel predictor (spec conv + 3 residual blocks).
// ============================================================
#define PRED_SMEM ((100*52 + 64*52 + 64*52 + 16000)*4)

__device__ __forceinline__ void pred_conv3(
    const float* src, float* dst, const float* rsd, float* wbuf,
    const float* __restrict__ wsrc, const float* __restrict__ bsrc,
    int plo, int phi, int l0, int hq, int pb, int tid){
    __syncthreads();
    for (int idx = tid; idx < 64*192; idx += 256){
        int h = idx/192, ck = idx%192;
        wbuf[ck*64 + h] = wsrc[h*192 + ck];
    }
    __syncthreads();
    uint64_t acc[2][3];
    #pragma unroll
    for (int m = 0; m < 2; m++){
        uint64_t bp = pack2f(bsrc[hq*4 + 2*m], bsrc[hq*4 + 2*m + 1]);
        acc[m][0]=bp; acc[m][1]=bp; acc[m][2]=bp;
    }
    for (int c = 0; c < 64; c++){
        float xv[5];
        #pragma unroll
        for (int m = 0; m < 5; m++) xv[m] = src[c*52 + pb + 1 + m];
        #pragma unroll
        for (int k = 0; k < 3; k++){
            ulonglong2 wp = *(const ulonglong2*)&wbuf[(c*3 + k)*64 + hq*4];
            #pragma unroll
            for (int j = 0; j < 3; j++){
                uint64_t xb = bcast2f(xv[j + k]);
                fma2(acc[0][j], wp.x, xb);
                fma2(acc[1][j], wp.y, xb);
            }
        }
    }
    #pragma unroll
    for (int m = 0; m < 2; m++)
    #pragma unroll
    for (int j = 0; j < 3; j++){
        int p = pb + j;
        if (p >= plo && p <= phi){
            int gl = l0 - 8 + p;
            bool ok = (gl >= 0 && gl < L_);
            float2 u = unpack2f(acc[m][j]);
            int ch0 = hq*4 + 2*m;
            float v0 = lrelu(u.x), v1 = lrelu(u.y);
            if (rsd){ v0 += rsd[ch0*52 + p + 2]; v1 += rsd[(ch0+1)*52 + p + 2]; }
            dst[ch0*52 + p + 2]     = ok ? v0 : 0.f;
            dst[(ch0+1)*52 + p + 2] = ok ? v1 : 0.f;
        }
    }
}

__global__ void __launch_bounds__(256)
k_pred(const float* __restrict__ spec,
       const float* __restrict__ kp_w, const float* __restrict__ kp_b,
       const float* __restrict__ rb_w1, const float* __restrict__ rb_b1,
       const float* __restrict__ rb_w2, const float* __restrict__ rb_b2){
    extern __shared__ float sm[];
    float* sspec = sm;
    float* bufA  = sm + 100*52;
    float* bufB  = bufA + 64*52;
    float* wbuf  = bufB + 64*52;
    int b = blockIdx.x, ls = blockIdx.y;
    int l0 = ls*32;
    int tid = threadIdx.x;
    int hq = tid >> 4;
    int pb = (tid & 15) * 3;

    const float* sp = spec + b*100*L_;
    for (int idx = tid; idx < 100*52; idx += 256){
        int c = idx/52, q = idx%52;
        int gl = l0 - 10 + q;
        sspec[c*52 + q] = (gl >= 0 && gl < L_) ? sp[c*L_ + gl] : 0.f;
    }
    uint64_t acc[2][3];
    #pragma unroll
    for (int m = 0; m < 2; m++){
        uint64_t bp = pack2f(kp_b[hq*4 + 2*m], kp_b[hq*4 + 2*m + 1]);
        acc[m][0]=bp; acc[m][1]=bp; acc[m][2]=bp;
    }
    for (int chunk = 0; chunk < 2; chunk++){
        __syncthreads();
        for (int idx = tid; idx < 16000; idx += 256){
            int h = idx/250, ck = idx%250;
            wbuf[ck*64 + h] = kp_w[h*500 + chunk*250 + ck];
        }
        __syncthreads();
        for (int c2 = 0; c2 < 50; c2++){
            int c = chunk*50 + c2;
            float xv[7];
            #pragma unroll
            for (int m = 0; m < 7; m++) xv[m] = sspec[c*52 + pb + m];
            #pragma unroll
            for (int k = 0; k < 5; k++){
                ulonglong2 wp = *(const ulonglong2*)&wbuf[(c2*5 + k)*64 + hq*4];
                #pragma unroll
                for (int j = 0; j < 3; j++){
                    uint64_t xb = bcast2f(xv[j + k]);
                    fma2(acc[0][j], wp.x, xb);
                    fma2(acc[1][j], wp.y, xb);
                }
            }
        }
    }
    #pragma unroll
    for (int m = 0; m < 2; m++)
    #pragma unroll
    for (int j = 0; j < 3; j++){
        int p = pb + j;
        if (p >= 2 && p <= 45){
            int gl = l0 - 8 + p;
            bool ok = (gl >= 0 && gl < L_);
            float2 u = unpack2f(acc[m][j]);
            int ch0 = hq*4 + 2*m;
            bufA[ch0*52 + p + 2]     = ok ? u.x : 0.f;
            bufA[(ch0+1)*52 + p + 2] = ok ? u.y : 0.f;
        }
    }
    #pragma unroll 1
    for (int i = 0; i < 3; i++){
        pred_conv3(bufA, bufB, nullptr, wbuf, rb_w1 + i*12288, rb_b1 + i*64,
                   3+2*i, 44-2*i, l0, hq, pb, tid);
        pred_conv3(bufB, bufA, bufA,    wbuf, rb_w2 + i*12288, rb_b2 + i*64,
                   4+2*i, 43-2*i, l0, hq, pb, tid);
    }
    __syncthreads();
    #pragma unroll
    for (int m = 0; m < 2; m++)
    #pragma unroll
    for (int j = 0; j < 3; j++){
        int p = pb + j;
        if (p >= 8 && p <= 39){
            int l = l0 - 8 + p;
            int ch0 = hq*4 + 2*m;
            g_F0[(b*H_ + ch0    )*L_ + l] = bufA[ch0*52 + p + 2];
            g_F0[(b*H_ + ch0 + 1)*L_ + l] = bufA[(ch0+1)*52 + p + 2];
        }
    }
}

// ============================================================
// K6: bias conv (64->256, K=3, pad 1) -> g_BS[b][bc][l]
// ============================================================
__global__ void k_biasconv(const float* __restrict__ w, const float* __restrict__ bias){
    int b = blockIdx.x, lt = blockIdx.y, bct = blockIdx.z;
    int tid = threadIdx.x;
    __shared__ float xs[64][36];
    __shared__ __align__(16) float ws[192][64];
    const float* in = &g_F0[b*H_*L_];
    int l0 = lt*32, bc0 = bct*64;
    for (int idx = tid; idx < 64*34; idx += 256){
        int c = idx / 34, p = idx % 34;
        int t = l0 - 1 + p;
        xs[c][p] = (t >= 0 && t < L_) ? in[c*L_ + t] : 0.f;
    }
    for (int idx = tid; idx < 64*192; idx += 256){
        int h = idx / 192, ck = idx % 192;
        ws[ck][h] = w[(bc0 + h)*192 + ck];
    }
    __syncthreads();
    int hq = tid >> 5, li = tid & 31;
    uint64_t acc2[4];
    #pragma unroll
    for (int m = 0; m < 4; m++)
        acc2[m] = pack2f(bias[bc0 + hq*8 + 2*m], bias[bc0 + hq*8 + 2*m + 1]);
    for (int c = 0; c < 64; c++){
        #pragma unroll
        for (int k = 0; k < 3; k++){
            uint64_t xb = bcast2f(xs[c][li + k]);
            const float* wr = &ws[c*3 + k][hq*8];
            ulonglong2 wA = *(const ulonglong2*)wr;
            ulonglong2 wB = *(const ulonglong2*)(wr + 4);
            fma2(acc2[0], wA.x, xb);
            fma2(acc2[1], wA.y, xb);
            fma2(acc2[2], wB.x, xb);
            fma2(acc2[3], wB.y, xb);
        }
    }
    int l = l0 + li;
    #pragma unroll
    for (int m = 0; m < 4; m++){
        float2 p = unpack2f(acc2[m]);
        g_BS[(b*256 + bc0 + hq*8 + 2*m    )*L_ + l] = p.x;
        g_BS[(b*256 + bc0 + hq*8 + 2*m + 1)*L_ + l] = p.y;
    }
}

// ============================================================
// K5: kern conv as GEMM (f32x2), X staged as pre-duplicated
// (x,x) pairs -> zero broadcast MOVs in the inner loop.
// Thread (ty,tx): 8 kc (pairs) x 8 n.  Xs2 thread stride 20
// floats (80B, 16B-aligned, <=2 crossbar phases).
// ============================================================
__global__ void __launch_bounds__(256)
k_kern_gemm(const float* __restrict__ A, const float* __restrict__ Ab){
    int kc0 = blockIdx.x * 128;
    int n0  = blockIdx.y * 128;
    int b   = n0 / L_;
    int l0w = n0 % L_;
    int tid = threadIdx.x;
    int ty = tid / 16, tx = tid % 16;
    __shared__ __align__(16) float As[16][128];
    __shared__ __align__(16) float Xs2[16][320];   // 16 thr-groups x 20 floats
    const float* F = &g_F0[b*H_*L_];

    uint64_t acc2[4][8];
    #pragma unroll
    for (int m = 0; m < 4; m++){
        uint64_t bp = pack2f(Ab[kc0 + ty*8 + 2*m], Ab[kc0 + ty*8 + 2*m + 1]);
        #pragma unroll
        for (int j = 0; j < 8; j++) acc2[m][j] = bp;
    }
    int arow = tid >> 1, ac0 = (tid & 1) * 8;
    int xrr = tid >> 4;                     // staging row 0..15
    for (int bk = 0; bk < 12; bk++){
        int r0 = bk*16;
        float4 v0 = *(const float4*)&A[(kc0 + arow)*192 + r0 + ac0];
        float4 v1 = *(const float4*)&A[(kc0 + arow)*192 + r0 + ac0 + 4];
        As[ac0+0][arow] = v0.x; As[ac0+1][arow] = v0.y;
        As[ac0+2][arow] = v0.z; As[ac0+3][arow] = v0.w;
        As[ac0+4][arow] = v1.x; As[ac0+5][arow] = v1.y;
        As[ac0+6][arow] = v1.z; As[ac0+7][arow] = v1.w;
        {
            int r = r0 + xrr;
            int hh = r/3, k = r%3;
            float* xrow = &Xs2[xrr][tx*20];
            #pragma unroll
            for (int q = 0; q < 8; q++){
                int t = l0w + tx*8 + q + k - 1;
                float v = (t >= 0 && t < L_) ? F[hh*L_ + t] : 0.f;
                *(uint64_t*)&xrow[2*q] = bcast2f(v);
            }
        }
        __syncthreads();
        #pragma unroll
        for (int kk = 0; kk < 16; kk++){
            ulonglong2 aA = *(const ulonglong2*)&As[kk][ty*8];
            ulonglong2 aB = *(const ulonglong2*)&As[kk][ty*8 + 4];
            uint64_t a2[4] = {aA.x, aA.y, aB.x, aB.y};
            const float* xrow = &Xs2[kk][tx*20];
            ulonglong2 x0 = *(const ulonglong2*)xrow;
            ulonglong2 x1 = *(const ulonglong2*)(xrow + 4);
            ulonglong2 x2 = *(const ulonglong2*)(xrow + 8);
            ulonglong2 x3 = *(const ulonglong2*)(xrow + 12);
            uint64_t xb[8] = {x0.x, x0.y, x1.x, x1.y, x2.x, x2.y, x3.x, x3.y};
            #pragma unroll
            for (int j = 0; j < 8; j++)
                #pragma unroll
                for (int m = 0; m < 4; m++)
                    fma2(acc2[m][j], a2[m], xb[j]);
        }
        __syncthreads();
    }
    #pragma unroll
    for (int j = 0; j < 8; j++){
        int n = n0 + tx*8 + j;
        #pragma unroll
        for (int m = 0; m < 4; m++){
            float2 p = unpack2f(acc2[m][j]);
            *(float2*)&g_KT[n*KC_ + kc0 + ty*8 + 2*m] = p;
        }
    }
}

// ============================================================
// K7: fused lrelu -> dilated conv (32->32,K=3,pad D) -> lrelu into g_C
// (R7 version: 256 thr, 256-sample tiles, templated dilation)
// ============================================================
#define DCONV_SMEM ((32*312 + 3072)*4)
template<int D>
__global__ void __launch_bounds__(256)
k_dconv(const float* __restrict__ w, const float* __restrict__ bias){
    extern __shared__ float sm[];
    float* xs = sm;           // 32 x 312 stride
    float* ws = sm + 32*312;  // [k][i][o]
    int b  = blockIdx.y;
    int t0 = blockIdx.x * 256;
    int tid = threadIdx.x;
    const int W = 256 + 2*D;
    const float* Hb = &g_H[b*NCH*T_FULL];
    for (int idx = tid; idx < NCH*W; idx += 256){
        int c = idx / W, p = idx % W;
        int t = t0 - D + p;
        xs[c*312 + p] = (t >= 0 && t < T_FULL) ? lrelu(Hb[c*T_FULL + t]) : 0.f;
    }
    for (int idx = tid; idx < 3072; idx += 256){
        int o = idx / 96, rem = idx % 96;
        int i = rem / 3, k = rem % 3;
        ws[k*1024 + i*32 + o] = w[idx];
    }
    __syncthreads();
    int o0 = (tid >> 5) * 4;
    int s0 = (tid & 31) * 8;
    uint64_t acc[2][8];
    #pragma unroll
    for (int m = 0; m < 2; m++){
        uint64_t bp = pack2f(bias[o0 + 2*m], bias[o0 + 2*m + 1]);
        #pragma unroll
        for (int j = 0; j < 8; j++) acc[m][j] = bp;
    }
    for (int i = 0; i < NCH; i++){
        const float* xr = &xs[i*312 + s0];
        #pragma unroll
        for (int k = 0; k < 3; k++){
            ulonglong2 wp = *(const ulonglong2*)&ws[k*1024 + i*32 + o0];
            #pragma unroll
            for (int j = 0; j < 8; j++){
                uint64_t xb = bcast2f(xr[j + k*D]);
                fma2(acc[0][j], wp.x, xb);
                fma2(acc[1][j], wp.y, xb);
            }
        }
    }
    float* Cb = &g_C[b*NCH*T_FULL];
    #pragma unroll
    for (int cc = 0; cc < 4; cc++){
        float tmp[8];
        #pragma unroll
        for (int j = 0; j < 8; j++){
            float2 u = unpack2f(acc[cc>>1][j]);
            tmp[j] = lrelu((cc & 1) ? u.y : u.x);
        }
        float* dst = &Cb[(o0 + cc)*T_FULL + t0 + s0];
        *(float4*)dst     = make_float4(tmp[0], tmp[1], tmp[2], tmp[3]);
        *(float4*)(dst+4) = make_float4(tmp[4], tmp[5], tmp[6], tmp[7]);
    }
}

// ============================================================
// K8: location-variable conv + bias + gating + residual (fused)
// (R7 version: 256 thr, one block per (l, b), full segment)
// ============================================================
#define LVC_SMEM ((32*264 + 6144)*4)
__global__ void __launch_bounds__(256)
k_lvc(int layer, float* __restrict__ outp){
    extern __shared__ float sm[];
    float* xs  = sm;            // 32 x 264 stride (258 used)
    float* ksh = sm + 32*264;   // [k][c][o]
    int b = blockIdx.y, l = blockIdx.x;
    int tid = threadIdx.x;
    const float* Cb  = &g_C[b*NCH*T_FULL];
    const float* KTb = &g_KT[(b*L_ + l)*KC_ + layer*6144];
    int tseg = l*HOP_;
    for (int idx = tid; idx < 32*258; idx += 256){
        int c = idx / 258, p = idx % 258;
        int t = tseg - 1 + p;
        xs[c*264 + p] = (t >= 0 && t < T_FULL) ? Cb[c*T_FULL + t] : 0.f;
    }
    const float4* K4 = (const float4*)KTb;
    for (int i4 = tid; i4 < 1536; i4 += 256){
        float4 v = K4[i4];
        float vv[4] = {v.x, v.y, v.z, v.w};
        int base = i4*4;
        #pragma unroll
        for (int e = 0; e < 4; e++){
            int idx = base + e;
            int c = idx / 192, rem = idx % 192;
            int o = rem / 3, k = rem % 3;
            ksh[k*2048 + c*64 + o] = vv[e];
        }
    }
    __syncthreads();
    int o0 = (tid >> 5) * 4;
    int s0 = (tid & 31) * 8;
    const float* Bb = &g_BS[(b*256 + layer*64)*L_];
    uint64_t accL[2][8], accH[2][8];
    #pragma unroll
    for (int m = 0; m < 2; m++){
        uint64_t bl = pack2f(Bb[(o0 + 2*m)*L_ + l],      Bb[(o0 + 2*m + 1)*L_ + l]);
        uint64_t bh = pack2f(Bb[(o0 + 2*m + 32)*L_ + l], Bb[(o0 + 2*m + 33)*L_ + l]);
        #pragma unroll
        for (int j = 0; j < 8; j++){ accL[m][j] = bl; accH[m][j] = bh; }
    }
    for (int c = 0; c < NCH; c++){
        const float* xr = &xs[c*264 + s0];
        float4 xa = *(const float4*)xr;
        float4 xbv = *(const float4*)(xr + 4);
        float2 xc = *(const float2*)(xr + 8);
        float xw[10] = {xa.x, xa.y, xa.z, xa.w, xbv.x, xbv.y, xbv.z, xbv.w, xc.x, xc.y};
        #pragma unroll
        for (int k = 0; k < 3; k++){
            ulonglong2 wl = *(const ulonglong2*)&ksh[k*2048 + c*64 + o0];
            ulonglong2 wh = *(const ulonglong2*)&ksh[k*2048 + c*64 + o0 + 32];
            #pragma unroll
            for (int j = 0; j < 8; j++){
                uint64_t x = bcast2f(xw[j + k]);
                fma2(accL[0][j], wl.x, x);
                fma2(accL[1][j], wl.y, x);
                fma2(accH[0][j], wh.x, x);
                fma2(accH[1][j], wh.y, x);
            }
        }
    }
    float* Hb = &g_H[b*NCH*T_FULL];
    float* Ob = outp ? &outp[b*NCH*T_FULL] : Hb;
    #pragma unroll
    for (int cc = 0; cc < 4; cc++){
        int oc = o0 + cc;
        const float* Hrow = &Hb[oc*T_FULL + tseg + s0];
        float4 r0 = *(const float4*)Hrow;
        float4 r1 = *(const float4*)(Hrow + 4);
        float rr[8] = {r0.x, r0.y, r0.z, r0.w, r1.x, r1.y, r1.z, r1.w};
        float tmp[8];
        #pragma unroll
        for (int j = 0; j < 8; j++){
            float2 uL = unpack2f(accL[cc>>1][j]);
            float2 uH = unpack2f(accH[cc>>1][j]);
            float aL = (cc & 1) ? uL.y : uL.x;
            float aH = (cc & 1) ? uH.y : uH.x;
            float sg = 1.f / (1.f + __expf(-aL));
            float th = tanhf(aH);
            tmp[j] = sg*th + rr[j];
        }
        float* dst = &Ob[oc*T_FULL + tseg + s0];
        *(float4*)dst     = make_float4(tmp[0], tmp[1], tmp[2], tmp[3]);
        *(float4*)(dst+4) = make_float4(tmp[4], tmp[5], tmp[6], tmp[7]);
    }
}

// ============================================================
extern "C" void kernel_launch(void* const* d_in, const int* in_sizes, int n_in,
                              void* d_out, int out_size){
    const float* hidden  = (const float*)d_in[0];
    const float* spec    = (const float*)d_in[1];
    const float* convt_w = (const float*)d_in[2];
    const float* convt_b = (const float*)d_in[3];
    const float* kp_in_w = (const float*)d_in[4];
    const float* kp_in_b = (const float*)d_in[5];
    const float* rb_w1   = (const float*)d_in[6];
    const float* rb_b1   = (const float*)d_in[7];
    const float* rb_w2   = (const float*)d_in[8];
    const float* rb_b2   = (const float*)d_in[9];
    const float* kern_w  = (const float*)d_in[10];
    const float* kern_b  = (const float*)d_in[11];
    const float* bias_w  = (const float*)d_in[12];
    const float* bias_b  = (const float*)d_in[13];
    const float* lvc_w   = (const float*)d_in[14];
    const float* lvc_b   = (const float*)d_in[15];

    cudaFuncSetAttribute(k_pred, cudaFuncAttributeMaxDynamicSharedMemorySize, PRED_SMEM);
    cudaFuncSetAttribute(k_lvc,  cudaFuncAttributeMaxDynamicSharedMemorySize, LVC_SMEM);
    cudaFuncSetAttribute(k_dconv<1>,  cudaFuncAttributeMaxDynamicSharedMemorySize, DCONV_SMEM);
    cudaFuncSetAttribute(k_dconv<3>,  cudaFuncAttributeMaxDynamicSharedMemorySize, DCONV_SMEM);
    cudaFuncSetAttribute(k_dconv<9>,  cudaFuncAttributeMaxDynamicSharedMemorySize, DCONV_SMEM);
    cudaFuncSetAttribute(k_dconv<27>, cudaFuncAttributeMaxDynamicSharedMemorySize, DCONV_SMEM);

    // position 0..2
    k_convT<<<dim3(256, B_), 256>>>(hidden, convt_w, convt_b);
    k_pred<<<dim3(B_, 8), 256, PRED_SMEM>>>(spec, kp_in_w, kp_in_b,
                                            rb_w1, rb_b1, rb_w2, rb_b2);
    k_biasconv<<<dim3(B_, 8, 4), 256>>>(bias_w, bias_b);
    // position 3 -> profiled by ncu (-s 5 with 2 harness launches ahead)
    k_kern_gemm<<<dim3(KC_/128, (B_*L_)/128), 256>>>(kern_w, kern_b);

    for (int i = 0; i < 4; i++){
        const float* wi = lvc_w + i*3072;
        const float* bi = lvc_b + i*32;
        dim3 dg(T_FULL/256, B_);
        if      (i == 0) k_dconv<1> <<<dg, 256, DCONV_SMEM>>>(wi, bi);
        else if (i == 1) k_dconv<3> <<<dg, 256, DCONV_SMEM>>>(wi, bi);
        else if (i == 2) k_dconv<9> <<<dg, 256, DCONV_SMEM>>>(wi, bi);
        else             k_dconv<27><<<dg, 256, DCONV_SMEM>>>(wi, bi);
        k_lvc<<<dim3(L_, B_), 256, LVC_SMEM>>>(i, (i == 3) ? (float*)d_out : nullptr);
    }
}

// round 11
// speedup vs baseline: 1.0953x; 1.0217x over previous
#include <cuda_runtime.h>
#include <cstdint>
#include <math.h>

#define B_     4
#define NCH    32
#define T_FULL 65536
#define T_IN   8192
#define L_     256
#define HOP_   256
#define H_     64
#define KC_    24576

// ---- scratch (device globals; no allocation allowed) ----
__device__ float g_H [B_*NCH*T_FULL];
__device__ float g_C [B_*NCH*T_FULL];
__device__ float g_F0[B_*H_*L_];
__device__ float g_KT[B_*L_*KC_];       // predicted kernels [n=b*L+l][kc]
__device__ float g_BS[B_*256*L_];       // predicted biases [b][bc][l]

__device__ __forceinline__ float lrelu(float x){ return x >= 0.f ? x : 0.2f*x; }

// ---- packed f32x2 helpers ----
__device__ __forceinline__ uint64_t pack2f(float lo, float hi){
    uint64_t r; asm("mov.b64 %0, {%1, %2};" : "=l"(r) : "f"(lo), "f"(hi)); return r;
}
__device__ __forceinline__ uint64_t bcast2f(float x){ return pack2f(x, x); }
__device__ __forceinline__ void fma2(uint64_t& d, uint64_t a, uint64_t b){
    asm("fma.rn.f32x2 %0, %1, %2, %0;" : "+l"(d) : "l"(a), "l"(b));
}
__device__ __forceinline__ float2 unpack2f(uint64_t v){
    float2 r; asm("mov.b64 {%0, %1}, %2;" : "=f"(r.x), "=f"(r.y) : "l"(v)); return r;
}

// ============================================================
// K1: conv_transpose1d  (stride 8, K=16, pad 4)
// ============================================================
__global__ void k_convT(const float* __restrict__ x, const float* __restrict__ w,
                        const float* __restrict__ bias){
    int b  = blockIdx.y;
    int t0 = blockIdx.x * 256;
    int tid = threadIdx.x;
    int r = tid & 7, o = tid >> 3;
    __shared__ float xs[NCH*36];
    const float* xb = x + b*NCH*T_IN;
    int jbase = t0/8 - 1;
    for (int idx = tid; idx < NCH*34; idx += 256){
        int c = idx / 34, p = idx % 34;
        int j = jbase + p;
        xs[c*36 + p] = (j >= 0 && j < T_IN) ? xb[c*T_IN + j] : 0.f;
    }
    __syncthreads();
    float acc[32];
    float bv = bias[o];
    #pragma unroll
    for (int s = 0; s < 32; s++) acc[s] = bv;
    int off = (r + 4) & 7;
    int e   = (off >= 4) ? 1 : 0;
    for (int i = 0; i < NCH; i++){
        float w1 = w[(i*32 + o)*16 + r];
        float w2 = w[(i*32 + o)*16 + r + 8];
        const float* xr = &xs[i*36 + e];
        float vp = xr[0];
        #pragma unroll
        for (int s = 0; s < 32; s++){
            float v = xr[s + 1];
            acc[s] += w1*v + w2*vp;
            vp = v;
        }
    }
    float* out = &g_H[(b*NCH + o)*T_FULL];
    #pragma unroll
    for (int s = 0; s < 32; s++) out[t0 + off + 8*s] = acc[s];
}

// ============================================================
// K2: FUSED kernel predictor (spec conv + 3 residual blocks).
// ============================================================
#define PRED_SMEM ((100*52 + 64*52 + 64*52 + 16000)*4)

__device__ __forceinline__ void pred_conv3(
    const float* src, float* dst, const float* rsd, float* wbuf,
    const float* __restrict__ wsrc, const float* __restrict__ bsrc,
    int plo, int phi, int l0, int hq, int pb, int tid){
    __syncthreads();
    for (int idx = tid; idx < 64*192; idx += 256){
        int h = idx/192, ck = idx%192;
        wbuf[ck*64 + h] = wsrc[h*192 + ck];
    }
    __syncthreads();
    uint64_t acc[2][3];
    #pragma unroll
    for (int m = 0; m < 2; m++){
        uint64_t bp = pack2f(bsrc[hq*4 + 2*m], bsrc[hq*4 + 2*m + 1]);
        acc[m][0]=bp; acc[m][1]=bp; acc[m][2]=bp;
    }
    for (int c = 0; c < 64; c++){
        float xv[5];
        #pragma unroll
        for (int m = 0; m < 5; m++) xv[m] = src[c*52 + pb + 1 + m];
        #pragma unroll
        for (int k = 0; k < 3; k++){
            ulonglong2 wp = *(const ulonglong2*)&wbuf[(c*3 + k)*64 + hq*4];
            #pragma unroll
            for (int j = 0; j < 3; j++){
                uint64_t xb = bcast2f(xv[j + k]);
                fma2(acc[0][j], wp.x, xb);
                fma2(acc[1][j], wp.y, xb);
            }
        }
    }
    #pragma unroll
    for (int m = 0; m < 2; m++)
    #pragma unroll
    for (int j = 0; j < 3; j++){
        int p = pb + j;
        if (p >= plo && p <= phi){
            int gl = l0 - 8 + p;
            bool ok = (gl >= 0 && gl < L_);
            float2 u = unpack2f(acc[m][j]);
            int ch0 = hq*4 + 2*m;
            float v0 = lrelu(u.x), v1 = lrelu(u.y);
            if (rsd){ v0 += rsd[ch0*52 + p + 2]; v1 += rsd[(ch0+1)*52 + p + 2]; }
            dst[ch0*52 + p + 2]     = ok ? v0 : 0.f;
            dst[(ch0+1)*52 + p + 2] = ok ? v1 : 0.f;
        }
    }
}

__global__ void __launch_bounds__(256)
k_pred(const float* __restrict__ spec,
       const float* __restrict__ kp_w, const float* __restrict__ kp_b,
       const float* __restrict__ rb_w1, const float* __restrict__ rb_b1,
       const float* __restrict__ rb_w2, const float* __restrict__ rb_b2){
    extern __shared__ float sm[];
    float* sspec = sm;
    float* bufA  = sm + 100*52;
    float* bufB  = bufA + 64*52;
    float* wbuf  = bufB + 64*52;
    int b = blockIdx.x, ls = blockIdx.y;
    int l0 = ls*32;
    int tid = threadIdx.x;
    int hq = tid >> 4;
    int pb = (tid & 15) * 3;

    const float* sp = spec + b*100*L_;
    for (int idx = tid; idx < 100*52; idx += 256){
        int c = idx/52, q = idx%52;
        int gl = l0 - 10 + q;
        sspec[c*52 + q] = (gl >= 0 && gl < L_) ? sp[c*L_ + gl] : 0.f;
    }
    uint64_t acc[2][3];
    #pragma unroll
    for (int m = 0; m < 2; m++){
        uint64_t bp = pack2f(kp_b[hq*4 + 2*m], kp_b[hq*4 + 2*m + 1]);
        acc[m][0]=bp; acc[m][1]=bp; acc[m][2]=bp;
    }
    for (int chunk = 0; chunk < 2; chunk++){
        __syncthreads();
        for (int idx = tid; idx < 16000; idx += 256){
            int h = idx/250, ck = idx%250;
            wbuf[ck*64 + h] = kp_w[h*500 + chunk*250 + ck];
        }
        __syncthreads();
        for (int c2 = 0; c2 < 50; c2++){
            int c = chunk*50 + c2;
            float xv[7];
            #pragma unroll
            for (int m = 0; m < 7; m++) xv[m] = sspec[c*52 + pb + m];
            #pragma unroll
            for (int k = 0; k < 5; k++){
                ulonglong2 wp = *(const ulonglong2*)&wbuf[(c2*5 + k)*64 + hq*4];
                #pragma unroll
                for (int j = 0; j < 3; j++){
                    uint64_t xb = bcast2f(xv[j + k]);
                    fma2(acc[0][j], wp.x, xb);
                    fma2(acc[1][j], wp.y, xb);
                }
            }
        }
    }
    #pragma unroll
    for (int m = 0; m < 2; m++)
    #pragma unroll
    for (int j = 0; j < 3; j++){
        int p = pb + j;
        if (p >= 2 && p <= 45){
            int gl = l0 - 8 + p;
            bool ok = (gl >= 0 && gl < L_);
            float2 u = unpack2f(acc[m][j]);
            int ch0 = hq*4 + 2*m;
            bufA[ch0*52 + p + 2]     = ok ? u.x : 0.f;
            bufA[(ch0+1)*52 + p + 2] = ok ? u.y : 0.f;
        }
    }
    #pragma unroll 1
    for (int i = 0; i < 3; i++){
        pred_conv3(bufA, bufB, nullptr, wbuf, rb_w1 + i*12288, rb_b1 + i*64,
                   3+2*i, 44-2*i, l0, hq, pb, tid);
        pred_conv3(bufB, bufA, bufA,    wbuf, rb_w2 + i*12288, rb_b2 + i*64,
                   4+2*i, 43-2*i, l0, hq, pb, tid);
    }
    __syncthreads();
    #pragma unroll
    for (int m = 0; m < 2; m++)
    #pragma unroll
    for (int j = 0; j < 3; j++){
        int p = pb + j;
        if (p >= 8 && p <= 39){
            int l = l0 - 8 + p;
            int ch0 = hq*4 + 2*m;
            g_F0[(b*H_ + ch0    )*L_ + l] = bufA[ch0*52 + p + 2];
            g_F0[(b*H_ + ch0 + 1)*L_ + l] = bufA[(ch0+1)*52 + p + 2];
        }
    }
}

// ============================================================
// K6: bias conv (64->256, K=3, pad 1) -> g_BS[b][bc][l]
// ============================================================
__global__ void k_biasconv(const float* __restrict__ w, const float* __restrict__ bias){
    int b = blockIdx.x, lt = blockIdx.y, bct = blockIdx.z;
    int tid = threadIdx.x;
    __shared__ float xs[64][36];
    __shared__ __align__(16) float ws[192][64];
    const float* in = &g_F0[b*H_*L_];
    int l0 = lt*32, bc0 = bct*64;
    for (int idx = tid; idx < 64*34; idx += 256){
        int c = idx / 34, p = idx % 34;
        int t = l0 - 1 + p;
        xs[c][p] = (t >= 0 && t < L_) ? in[c*L_ + t] : 0.f;
    }
    for (int idx = tid; idx < 64*192; idx += 256){
        int h = idx / 192, ck = idx % 192;
        ws[ck][h] = w[(bc0 + h)*192 + ck];
    }
    __syncthreads();
    int hq = tid >> 5, li = tid & 31;
    uint64_t acc2[4];
    #pragma unroll
    for (int m = 0; m < 4; m++)
        acc2[m] = pack2f(bias[bc0 + hq*8 + 2*m], bias[bc0 + hq*8 + 2*m + 1]);
    for (int c = 0; c < 64; c++){
        #pragma unroll
        for (int k = 0; k < 3; k++){
            uint64_t xb = bcast2f(xs[c][li + k]);
            const float* wr = &ws[c*3 + k][hq*8];
            ulonglong2 wA = *(const ulonglong2*)wr;
            ulonglong2 wB = *(const ulonglong2*)(wr + 4);
            fma2(acc2[0], wA.x, xb);
            fma2(acc2[1], wA.y, xb);
            fma2(acc2[2], wB.x, xb);
            fma2(acc2[3], wB.y, xb);
        }
    }
    int l = l0 + li;
    #pragma unroll
    for (int m = 0; m < 4; m++){
        float2 p = unpack2f(acc2[m]);
        g_BS[(b*256 + bc0 + hq*8 + 2*m    )*L_ + l] = p.x;
        g_BS[(b*256 + bc0 + hq*8 + 2*m + 1)*L_ + l] = p.y;
    }
}

// ============================================================
// K5: kern conv as GEMM (f32x2). Tile 128(kc) x 64(n), thread =
// 8 kc x 4 n. Lane->contiguous-n mapping: X reads are fully
// coalesced (lanes 0-15 contiguous 256B, 16-31 broadcast);
// A reads are 16-way broadcast. ~5 LSU phases per 16 fma2.
// ============================================================
__global__ void __launch_bounds__(256)
k_kern_gemm(const float* __restrict__ A, const float* __restrict__ Ab){
    int kc0 = blockIdx.x * 128;
    int n0  = blockIdx.y * 64;
    int b   = n0 / L_;
    int l0w = n0 % L_;
    int tid = threadIdx.x;
    int warp = tid >> 5, lane = tid & 31;
    int ty = (warp << 1) | (lane >> 4);   // 0..15 kc-group
    int tx = lane & 15;                   // 0..15 n-group (contiguous within half-warp)
    __shared__ __align__(16) float As[16][128];
    __shared__ __align__(16) float Xs[16][68];
    const float* F = &g_F0[b*H_*L_];

    uint64_t acc[4][4];
    #pragma unroll
    for (int m = 0; m < 4; m++){
        uint64_t bp = pack2f(Ab[kc0 + ty*8 + 2*m], Ab[kc0 + ty*8 + 2*m + 1]);
        #pragma unroll
        for (int j = 0; j < 4; j++) acc[m][j] = bp;
    }
    int arow = tid >> 1, ac0 = (tid & 1) * 8;
    int xrr = tid >> 4, xc0 = (tid & 15) * 4;
    for (int bk = 0; bk < 12; bk++){
        int r0 = bk*16;
        float4 v0 = *(const float4*)&A[(kc0 + arow)*192 + r0 + ac0];
        float4 v1 = *(const float4*)&A[(kc0 + arow)*192 + r0 + ac0 + 4];
        As[ac0+0][arow] = v0.x; As[ac0+1][arow] = v0.y;
        As[ac0+2][arow] = v0.z; As[ac0+3][arow] = v0.w;
        As[ac0+4][arow] = v1.x; As[ac0+5][arow] = v1.y;
        As[ac0+6][arow] = v1.z; As[ac0+7][arow] = v1.w;
        {
            int r = r0 + xrr;
            int hh = r/3, k = r%3;
            #pragma unroll
            for (int q = 0; q < 4; q++){
                int t = l0w + xc0 + q + k - 1;
                Xs[xrr][xc0+q] = (t >= 0 && t < L_) ? F[hh*L_ + t] : 0.f;
            }
        }
        __syncthreads();
        #pragma unroll
        for (int kk = 0; kk < 16; kk++){
            ulonglong2 aA = *(const ulonglong2*)&As[kk][ty*8];
            ulonglong2 aB = *(const ulonglong2*)&As[kk][ty*8 + 4];
            uint64_t a2[4] = {aA.x, aA.y, aB.x, aB.y};
            float4 xv = *(const float4*)&Xs[kk][tx*4];
            uint64_t xb[4] = {bcast2f(xv.x), bcast2f(xv.y), bcast2f(xv.z), bcast2f(xv.w)};
            #pragma unroll
            for (int j = 0; j < 4; j++)
                #pragma unroll
                for (int m = 0; m < 4; m++)
                    fma2(acc[m][j], a2[m], xb[j]);
        }
        __syncthreads();
    }
    #pragma unroll
    for (int j = 0; j < 4; j++){
        int n = n0 + tx*4 + j;
        #pragma unroll
        for (int m = 0; m < 4; m++){
            float2 p = unpack2f(acc[m][j]);
            *(float2*)&g_KT[n*KC_ + kc0 + ty*8 + 2*m] = p;
        }
    }
}

// ============================================================
// K7: fused lrelu -> dilated conv (32->32,K=3,pad D) -> lrelu into g_C
// ============================================================
#define DCONV_SMEM ((32*312 + 3072)*4)
template<int D>
__global__ void __launch_bounds__(256)
k_dconv(const float* __restrict__ w, const float* __restrict__ bias){
    extern __shared__ float sm[];
    float* xs = sm;           // 32 x 312 stride
    float* ws = sm + 32*312;  // [k][i][o]
    int b  = blockIdx.y;
    int t0 = blockIdx.x * 256;
    int tid = threadIdx.x;
    const int W = 256 + 2*D;
    const float* Hb = &g_H[b*NCH*T_FULL];
    for (int idx = tid; idx < NCH*W; idx += 256){
        int c = idx / W, p = idx % W;
        int t = t0 - D + p;
        xs[c*312 + p] = (t >= 0 && t < T_FULL) ? lrelu(Hb[c*T_FULL + t]) : 0.f;
    }
    for (int idx = tid; idx < 3072; idx += 256){
        int o = idx / 96, rem = idx % 96;
        int i = rem / 3, k = rem % 3;
        ws[k*1024 + i*32 + o] = w[idx];
    }
    __syncthreads();
    int o0 = (tid >> 5) * 4;
    int s0 = (tid & 31) * 8;
    uint64_t acc[2][8];
    #pragma unroll
    for (int m = 0; m < 2; m++){
        uint64_t bp = pack2f(bias[o0 + 2*m], bias[o0 + 2*m + 1]);
        #pragma unroll
        for (int j = 0; j < 8; j++) acc[m][j] = bp;
    }
    for (int i = 0; i < NCH; i++){
        const float* xr = &xs[i*312 + s0];
        #pragma unroll
        for (int k = 0; k < 3; k++){
            ulonglong2 wp = *(const ulonglong2*)&ws[k*1024 + i*32 + o0];
            #pragma unroll
            for (int j = 0; j < 8; j++){
                uint64_t xb = bcast2f(xr[j + k*D]);
                fma2(acc[0][j], wp.x, xb);
                fma2(acc[1][j], wp.y, xb);
            }
        }
    }
    float* Cb = &g_C[b*NCH*T_FULL];
    #pragma unroll
    for (int cc = 0; cc < 4; cc++){
        float tmp[8];
        #pragma unroll
        for (int j = 0; j < 8; j++){
            float2 u = unpack2f(acc[cc>>1][j]);
            tmp[j] = lrelu((cc & 1) ? u.y : u.x);
        }
        float* dst = &Cb[(o0 + cc)*T_FULL + t0 + s0];
        *(float4*)dst     = make_float4(tmp[0], tmp[1], tmp[2], tmp[3]);
        *(float4*)(dst+4) = make_float4(tmp[4], tmp[5], tmp[6], tmp[7]);
    }
}

// ============================================================
// K8: location-variable conv + bias + gating + residual (fused)
// ============================================================
#define LVC_SMEM ((32*264 + 6144)*4)
__global__ void __launch_bounds__(256)
k_lvc(int layer, float* __restrict__ outp){
    extern __shared__ float sm[];
    float* xs  = sm;            // 32 x 264 stride (258 used)
    float* ksh = sm + 32*264;   // [k][c][o]
    int b = blockIdx.y, l = blockIdx.x;
    int tid = threadIdx.x;
    const float* Cb  = &g_C[b*NCH*T_FULL];
    const float* KTb = &g_KT[(b*L_ + l)*KC_ + layer*6144];
    int tseg = l*HOP_;
    for (int idx = tid; idx < 32*258; idx += 256){
        int c = idx / 258, p = idx % 258;
        int t = tseg - 1 + p;
        xs[c*264 + p] = (t >= 0 && t < T_FULL) ? Cb[c*T_FULL + t] : 0.f;
    }
    const float4* K4 = (const float4*)KTb;
    for (int i4 = tid; i4 < 1536; i4 += 256){
        float4 v = K4[i4];
        float vv[4] = {v.x, v.y, v.z, v.w};
        int base = i4*4;
        #pragma unroll
        for (int e = 0; e < 4; e++){
            int idx = base + e;
            int c = idx / 192, rem = idx % 192;
            int o = rem / 3, k = rem % 3;
            ksh[k*2048 + c*64 + o] = vv[e];
        }
    }
    __syncthreads();
    int o0 = (tid >> 5) * 4;
    int s0 = (tid & 31) * 8;
    const float* Bb = &g_BS[(b*256 + layer*64)*L_];
    uint64_t accL[2][8], accH[2][8];
    #pragma unroll
    for (int m = 0; m < 2; m++){
        uint64_t bl = pack2f(Bb[(o0 + 2*m)*L_ + l],      Bb[(o0 + 2*m + 1)*L_ + l]);
        uint64_t bh = pack2f(Bb[(o0 + 2*m + 32)*L_ + l], Bb[(o0 + 2*m + 33)*L_ + l]);
        #pragma unroll
        for (int j = 0; j < 8; j++){ accL[m][j] = bl; accH[m][j] = bh; }
    }
    for (int c = 0; c < NCH; c++){
        const float* xr = &xs[c*264 + s0];
        float4 xa = *(const float4*)xr;
        float4 xbv = *(const float4*)(xr + 4);
        float2 xc = *(const float2*)(xr + 8);
        float xw[10] = {xa.x, xa.y, xa.z, xa.w, xbv.x, xbv.y, xbv.z, xbv.w, xc.x, xc.y};
        #pragma unroll
        for (int k = 0; k < 3; k++){
            ulonglong2 wl = *(const ulonglong2*)&ksh[k*2048 + c*64 + o0];
            ulonglong2 wh = *(const ulonglong2*)&ksh[k*2048 + c*64 + o0 + 32];
            #pragma unroll
            for (int j = 0; j < 8; j++){
                uint64_t x = bcast2f(xw[j + k]);
                fma2(accL[0][j], wl.x, x);
                fma2(accL[1][j], wl.y, x);
                fma2(accH[0][j], wh.x, x);
                fma2(accH[1][j], wh.y, x);
            }
        }
    }
    float* Hb = &g_H[b*NCH*T_FULL];
    float* Ob = outp ? &outp[b*NCH*T_FULL] : Hb;
    #pragma unroll
    for (int cc = 0; cc < 4; cc++){
        int oc = o0 + cc;
        const float* Hrow = &Hb[oc*T_FULL + tseg + s0];
        float4 r0 = *(const float4*)Hrow;
        float4 r1 = *(const float4*)(Hrow + 4);
        float rr[8] = {r0.x, r0.y, r0.z, r0.w, r1.x, r1.y, r1.z, r1.w};
        float tmp[8];
        #pragma unroll
        for (int j = 0; j < 8; j++){
            float2 uL = unpack2f(accL[cc>>1][j]);
            float2 uH = unpack2f(accH[cc>>1][j]);
            float aL = (cc & 1) ? uL.y : uL.x;
            float aH = (cc & 1) ? uH.y : uH.x;
            float sg = 1.f / (1.f + __expf(-aL));
            float th = tanhf(aH);
            tmp[j] = sg*th + rr[j];
        }
        float* dst = &Ob[oc*T_FULL + tseg + s0];
        *(float4*)dst     = make_float4(tmp[0], tmp[1], tmp[2], tmp[3]);
        *(float4*)(dst+4) = make_float4(tmp[4], tmp[5], tmp[6], tmp[7]);
    }
}

// ============================================================
extern "C" void kernel_launch(void* const* d_in, const int* in_sizes, int n_in,
                              void* d_out, int out_size){
    const float* hidden  = (const float*)d_in[0];
    const float* spec    = (const float*)d_in[1];
    const float* convt_w = (const float*)d_in[2];
    const float* convt_b = (const float*)d_in[3];
    const float* kp_in_w = (const float*)d_in[4];
    const float* kp_in_b = (const float*)d_in[5];
    const float* rb_w1   = (const float*)d_in[6];
    const float* rb_b1   = (const float*)d_in[7];
    const float* rb_w2   = (const float*)d_in[8];
    const float* rb_b2   = (const float*)d_in[9];
    const float* kern_w  = (const float*)d_in[10];
    const float* kern_b  = (const float*)d_in[11];
    const float* bias_w  = (const float*)d_in[12];
    const float* bias_b  = (const float*)d_in[13];
    const float* lvc_w   = (const float*)d_in[14];
    const float* lvc_b   = (const float*)d_in[15];

    cudaFuncSetAttribute(k_pred, cudaFuncAttributeMaxDynamicSharedMemorySize, PRED_SMEM);
    cudaFuncSetAttribute(k_lvc,  cudaFuncAttributeMaxDynamicSharedMemorySize, LVC_SMEM);
    cudaFuncSetAttribute(k_dconv<1>,  cudaFuncAttributeMaxDynamicSharedMemorySize, DCONV_SMEM);
    cudaFuncSetAttribute(k_dconv<3>,  cudaFuncAttributeMaxDynamicSharedMemorySize, DCONV_SMEM);
    cudaFuncSetAttribute(k_dconv<9>,  cudaFuncAttributeMaxDynamicSharedMemorySize, DCONV_SMEM);
    cudaFuncSetAttribute(k_dconv<27>, cudaFuncAttributeMaxDynamicSharedMemorySize, DCONV_SMEM);

    // position 0..2
    k_convT<<<dim3(256, B_), 256>>>(hidden, convt_w, convt_b);
    k_pred<<<dim3(B_, 8), 256, PRED_SMEM>>>(spec, kp_in_w, kp_in_b,
                                            rb_w1, rb_b1, rb_w2, rb_b2);
    k_biasconv<<<dim3(B_, 8, 4), 256>>>(bias_w, bias_b);
    // position 3 -> profiled by ncu
    k_kern_gemm<<<dim3(KC_/128, (B_*L_)/64), 256>>>(kern_w, kern_b);

    for (int i = 0; i < 4; i++){
        const float* wi = lvc_w + i*3072;
        const float* bi = lvc_b + i*32;
        dim3 dg(T_FULL/256, B_);
        if      (i == 0) k_dconv<1> <<<dg, 256, DCONV_SMEM>>>(wi, bi);
        else if (i == 1) k_dconv<3> <<<dg, 256, DCONV_SMEM>>>(wi, bi);
        else if (i == 2) k_dconv<9> <<<dg, 256, DCONV_SMEM>>>(wi, bi);
        else             k_dconv<27><<<dg, 256, DCONV_SMEM>>>(wi, bi);
        k_lvc<<<dim3(L_, B_), 256, LVC_SMEM>>>(i, (i == 3) ? (float*)d_out : nullptr);
    }
}

// round 12
// speedup vs baseline: 1.1535x; 1.0532x over previous
#include <cuda_runtime.h>
#include <cstdint>
#include <math.h>

#define B_     4
#define NCH    32
#define T_FULL 65536
#define T_IN   8192
#define L_     256
#define HOP_   256
#define H_     64
#define KC_    24576

// ---- scratch (device globals; no allocation allowed) ----
__device__ float g_H [B_*NCH*T_FULL];   // hidden state buffer A
__device__ float g_C [B_*NCH*T_FULL];   // hidden state buffer B (double-buffer)
__device__ float g_F0[B_*H_*L_];
__device__ float g_KT[B_*L_*KC_];       // predicted kernels [n=b*L+l][kc]
__device__ float g_BS[B_*256*L_];       // predicted biases [b][bc][l]

__device__ __forceinline__ float lrelu(float x){ return x >= 0.f ? x : 0.2f*x; }

// ---- packed f32x2 helpers ----
__device__ __forceinline__ uint64_t pack2f(float lo, float hi){
    uint64_t r; asm("mov.b64 %0, {%1, %2};" : "=l"(r) : "f"(lo), "f"(hi)); return r;
}
__device__ __forceinline__ uint64_t bcast2f(float x){ return pack2f(x, x); }
__device__ __forceinline__ void fma2(uint64_t& d, uint64_t a, uint64_t b){
    asm("fma.rn.f32x2 %0, %1, %2, %0;" : "+l"(d) : "l"(a), "l"(b));
}
__device__ __forceinline__ float2 unpack2f(uint64_t v){
    float2 r; asm("mov.b64 {%0, %1}, %2;" : "=f"(r.x), "=f"(r.y) : "l"(v)); return r;
}

// ============================================================
// K1: conv_transpose1d  (stride 8, K=16, pad 4) -> g_H
// ============================================================
__global__ void k_convT(const float* __restrict__ x, const float* __restrict__ w,
                        const float* __restrict__ bias){
    int b  = blockIdx.y;
    int t0 = blockIdx.x * 256;
    int tid = threadIdx.x;
    int r = tid & 7, o = tid >> 3;
    __shared__ float xs[NCH*36];
    const float* xb = x + b*NCH*T_IN;
    int jbase = t0/8 - 1;
    for (int idx = tid; idx < NCH*34; idx += 256){
        int c = idx / 34, p = idx % 34;
        int j = jbase + p;
        xs[c*36 + p] = (j >= 0 && j < T_IN) ? xb[c*T_IN + j] : 0.f;
    }
    __syncthreads();
    float acc[32];
    float bv = bias[o];
    #pragma unroll
    for (int s = 0; s < 32; s++) acc[s] = bv;
    int off = (r + 4) & 7;
    int e   = (off >= 4) ? 1 : 0;
    for (int i = 0; i < NCH; i++){
        float w1 = w[(i*32 + o)*16 + r];
        float w2 = w[(i*32 + o)*16 + r + 8];
        const float* xr = &xs[i*36 + e];
        float vp = xr[0];
        #pragma unroll
        for (int s = 0; s < 32; s++){
            float v = xr[s + 1];
            acc[s] += w1*v + w2*vp;
            vp = v;
        }
    }
    float* out = &g_H[(b*NCH + o)*T_FULL];
    #pragma unroll
    for (int s = 0; s < 32; s++) out[t0 + off + 8*s] = acc[s];
}

// ============================================================
// K2: FUSED kernel predictor (spec conv + 3 residual blocks).
// ============================================================
#define PRED_SMEM ((100*52 + 64*52 + 64*52 + 16000)*4)

__device__ __forceinline__ void pred_conv3(
    const float* src, float* dst, const float* rsd, float* wbuf,
    const float* __restrict__ wsrc, const float* __restrict__ bsrc,
    int plo, int phi, int l0, int hq, int pb, int tid){
    __syncthreads();
    for (int idx = tid; idx < 64*192; idx += 256){
        int h = idx/192, ck = idx%192;
        wbuf[ck*64 + h] = wsrc[h*192 + ck];
    }
    __syncthreads();
    uint64_t acc[2][3];
    #pragma unroll
    for (int m = 0; m < 2; m++){
        uint64_t bp = pack2f(bsrc[hq*4 + 2*m], bsrc[hq*4 + 2*m + 1]);
        acc[m][0]=bp; acc[m][1]=bp; acc[m][2]=bp;
    }
    for (int c = 0; c < 64; c++){
        float xv[5];
        #pragma unroll
        for (int m = 0; m < 5; m++) xv[m] = src[c*52 + pb + 1 + m];
        #pragma unroll
        for (int k = 0; k < 3; k++){
            ulonglong2 wp = *(const ulonglong2*)&wbuf[(c*3 + k)*64 + hq*4];
            #pragma unroll
            for (int j = 0; j < 3; j++){
                uint64_t xb = bcast2f(xv[j + k]);
                fma2(acc[0][j], wp.x, xb);
                fma2(acc[1][j], wp.y, xb);
            }
        }
    }
    #pragma unroll
    for (int m = 0; m < 2; m++)
    #pragma unroll
    for (int j = 0; j < 3; j++){
        int p = pb + j;
        if (p >= plo && p <= phi){
            int gl = l0 - 8 + p;
            bool ok = (gl >= 0 && gl < L_);
            float2 u = unpack2f(acc[m][j]);
            int ch0 = hq*4 + 2*m;
            float v0 = lrelu(u.x), v1 = lrelu(u.y);
            if (rsd){ v0 += rsd[ch0*52 + p + 2]; v1 += rsd[(ch0+1)*52 + p + 2]; }
            dst[ch0*52 + p + 2]     = ok ? v0 : 0.f;
            dst[(ch0+1)*52 + p + 2] = ok ? v1 : 0.f;
        }
    }
}

__global__ void __launch_bounds__(256)
k_pred(const float* __restrict__ spec,
       const float* __restrict__ kp_w, const float* __restrict__ kp_b,
       const float* __restrict__ rb_w1, const float* __restrict__ rb_b1,
       const float* __restrict__ rb_w2, const float* __restrict__ rb_b2){
    extern __shared__ float sm[];
    float* sspec = sm;
    float* bufA  = sm + 100*52;
    float* bufB  = bufA + 64*52;
    float* wbuf  = bufB + 64*52;
    int b = blockIdx.x, ls = blockIdx.y;
    int l0 = ls*32;
    int tid = threadIdx.x;
    int hq = tid >> 4;
    int pb = (tid & 15) * 3;

    const float* sp = spec + b*100*L_;
    for (int idx = tid; idx < 100*52; idx += 256){
        int c = idx/52, q = idx%52;
        int gl = l0 - 10 + q;
        sspec[c*52 + q] = (gl >= 0 && gl < L_) ? sp[c*L_ + gl] : 0.f;
    }
    uint64_t acc[2][3];
    #pragma unroll
    for (int m = 0; m < 2; m++){
        uint64_t bp = pack2f(kp_b[hq*4 + 2*m], kp_b[hq*4 + 2*m + 1]);
        acc[m][0]=bp; acc[m][1]=bp; acc[m][2]=bp;
    }
    for (int chunk = 0; chunk < 2; chunk++){
        __syncthreads();
        for (int idx = tid; idx < 16000; idx += 256){
            int h = idx/250, ck = idx%250;
            wbuf[ck*64 + h] = kp_w[h*500 + chunk*250 + ck];
        }
        __syncthreads();
        for (int c2 = 0; c2 < 50; c2++){
            int c = chunk*50 + c2;
            float xv[7];
            #pragma unroll
            for (int m = 0; m < 7; m++) xv[m] = sspec[c*52 + pb + m];
            #pragma unroll
            for (int k = 0; k < 5; k++){
                ulonglong2 wp = *(const ulonglong2*)&wbuf[(c2*5 + k)*64 + hq*4];
                #pragma unroll
                for (int j = 0; j < 3; j++){
                    uint64_t xb = bcast2f(xv[j + k]);
                    fma2(acc[0][j], wp.x, xb);
                    fma2(acc[1][j], wp.y, xb);
                }
            }
        }
    }
    #pragma unroll
    for (int m = 0; m < 2; m++)
    #pragma unroll
    for (int j = 0; j < 3; j++){
        int p = pb + j;
        if (p >= 2 && p <= 45){
            int gl = l0 - 8 + p;
            bool ok = (gl >= 0 && gl < L_);
            float2 u = unpack2f(acc[m][j]);
            int ch0 = hq*4 + 2*m;
            bufA[ch0*52 + p + 2]     = ok ? u.x : 0.f;
            bufA[(ch0+1)*52 + p + 2] = ok ? u.y : 0.f;
        }
    }
    #pragma unroll 1
    for (int i = 0; i < 3; i++){
        pred_conv3(bufA, bufB, nullptr, wbuf, rb_w1 + i*12288, rb_b1 + i*64,
                   3+2*i, 44-2*i, l0, hq, pb, tid);
        pred_conv3(bufB, bufA, bufA,    wbuf, rb_w2 + i*12288, rb_b2 + i*64,
                   4+2*i, 43-2*i, l0, hq, pb, tid);
    }
    __syncthreads();
    #pragma unroll
    for (int m = 0; m < 2; m++)
    #pragma unroll
    for (int j = 0; j < 3; j++){
        int p = pb + j;
        if (p >= 8 && p <= 39){
            int l = l0 - 8 + p;
            int ch0 = hq*4 + 2*m;
            g_F0[(b*H_ + ch0    )*L_ + l] = bufA[ch0*52 + p + 2];
            g_F0[(b*H_ + ch0 + 1)*L_ + l] = bufA[(ch0+1)*52 + p + 2];
        }
    }
}

// ============================================================
// K5: kern conv GEMM (f32x2), tile 128(kc) x 64(n).
// Extended with 2 tail block-rows (blockIdx.x 192,193) that
// compute the bias conv (bias_w rows) into g_BS.
// ============================================================
__global__ void __launch_bounds__(256)
k_kern_gemm(const float* __restrict__ A, const float* __restrict__ Ab,
            const float* __restrict__ Bw, const float* __restrict__ Bb){
    int kc0 = blockIdx.x * 128;
    bool is_bias = (kc0 >= KC_);
    int n0  = blockIdx.y * 64;
    int b   = n0 / L_;
    int l0w = n0 % L_;
    int tid = threadIdx.x;
    int warp = tid >> 5, lane = tid & 31;
    int ty = (warp << 1) | (lane >> 4);
    int tx = lane & 15;
    __shared__ __align__(16) float As[16][128];
    __shared__ __align__(16) float Xs[16][68];
    const float* F = &g_F0[b*H_*L_];
    const float* Arow_base = is_bias ? Bw : A;
    const float* bias_base = is_bias ? Bb : Ab;
    int row_off = is_bias ? (kc0 - KC_) : kc0;

    uint64_t acc[4][4];
    #pragma unroll
    for (int m = 0; m < 4; m++){
        uint64_t bp = pack2f(bias_base[row_off + ty*8 + 2*m],
                             bias_base[row_off + ty*8 + 2*m + 1]);
        #pragma unroll
        for (int j = 0; j < 4; j++) acc[m][j] = bp;
    }
    int arow = tid >> 1, ac0 = (tid & 1) * 8;
    int xrr = tid >> 4, xc0 = (tid & 15) * 4;
    for (int bk = 0; bk < 12; bk++){
        int r0 = bk*16;
        float4 v0 = *(const float4*)&Arow_base[(row_off + arow)*192 + r0 + ac0];
        float4 v1 = *(const float4*)&Arow_base[(row_off + arow)*192 + r0 + ac0 + 4];
        As[ac0+0][arow] = v0.x; As[ac0+1][arow] = v0.y;
        As[ac0+2][arow] = v0.z; As[ac0+3][arow] = v0.w;
        As[ac0+4][arow] = v1.x; As[ac0+5][arow] = v1.y;
        As[ac0+6][arow] = v1.z; As[ac0+7][arow] = v1.w;
        {
            int r = r0 + xrr;
            int hh = r/3, k = r%3;
            #pragma unroll
            for (int q = 0; q < 4; q++){
                int t = l0w + xc0 + q + k - 1;
                Xs[xrr][xc0+q] = (t >= 0 && t < L_) ? F[hh*L_ + t] : 0.f;
            }
        }
        __syncthreads();
        #pragma unroll
        for (int kk = 0; kk < 16; kk++){
            ulonglong2 aA = *(const ulonglong2*)&As[kk][ty*8];
            ulonglong2 aB = *(const ulonglong2*)&As[kk][ty*8 + 4];
            uint64_t a2[4] = {aA.x, aA.y, aB.x, aB.y};
            float4 xv = *(const float4*)&Xs[kk][tx*4];
            uint64_t xb[4] = {bcast2f(xv.x), bcast2f(xv.y), bcast2f(xv.z), bcast2f(xv.w)};
            #pragma unroll
            for (int j = 0; j < 4; j++)
                #pragma unroll
                for (int m = 0; m < 4; m++)
                    fma2(acc[m][j], a2[m], xb[j]);
        }
        __syncthreads();
    }
    if (!is_bias){
        #pragma unroll
        for (int j = 0; j < 4; j++){
            int n = n0 + tx*4 + j;
            #pragma unroll
            for (int m = 0; m < 4; m++){
                float2 p = unpack2f(acc[m][j]);
                *(float2*)&g_KT[n*KC_ + kc0 + ty*8 + 2*m] = p;
            }
        }
    } else {
        #pragma unroll
        for (int j = 0; j < 4; j++){
            int l = l0w + tx*4 + j;
            #pragma unroll
            for (int m = 0; m < 4; m++){
                float2 p = unpack2f(acc[m][j]);
                int bc = row_off + ty*8 + 2*m;
                g_BS[(b*256 + bc    )*L_ + l] = p.x;
                g_BS[(b*256 + bc + 1)*L_ + l] = p.y;
            }
        }
    }
}

// ============================================================
// K7+K8 FUSED: lrelu -> dilated conv -> lrelu (into smem sc)
// -> location-variable conv + bias + gating + residual.
// One block per (segment l, batch b). H double-buffered across
// layers (in: Hin, out: Hout) to avoid halo races.
// ============================================================
#define FUSED_SMEM ((32*312 + 3072 + 32*264 + 6144)*4)
template<int D>
__global__ void __launch_bounds__(256)
k_fused(int layer, const float* __restrict__ w, const float* __restrict__ bias,
        float* __restrict__ outp){
    extern __shared__ float sm[];
    float* sx  = sm;                    // 32 x 312: lrelu(Hin) window
    float* ws  = sm + 32*312;           // [k][i][o] 3072
    float* sc  = ws + 3072;             // 32 x 264 (258 used): conv out
    float* ksh = sc + 32*264;           // [k][c][o] 6144
    int b = blockIdx.y, l = blockIdx.x;
    int tid = threadIdx.x;
    int tseg = l*HOP_;
    const float* Hin  = (layer & 1) ? g_C : g_H;
    float* Hout = outp ? outp : ((layer & 1) ? g_H : g_C);
    const float* Hb = &Hin[b*NCH*T_FULL];

    // --- stage lrelu'd H window: q in [0, 258+2D), t = tseg-1-D+q ---
    const int W2 = 258 + 2*D;
    for (int idx = tid; idx < NCH*W2; idx += 256){
        int c = idx / W2, q = idx % W2;
        int t = tseg - 1 - D + q;
        sx[c*312 + q] = (t >= 0 && t < T_FULL) ? lrelu(Hb[c*T_FULL + t]) : 0.f;
    }
    // --- stage dconv weights [k][i][o] ---
    for (int idx = tid; idx < 3072; idx += 256){
        int o = idx / 96, rem = idx % 96;
        int i = rem / 3, k = rem % 3;
        ws[k*1024 + i*32 + o] = w[idx];
    }
    // --- stage LVC kernel tile [k][c][o] ---
    const float* KTb = &g_KT[(b*L_ + l)*KC_ + layer*6144];
    const float4* K4 = (const float4*)KTb;
    for (int i4 = tid; i4 < 1536; i4 += 256){
        float4 v = K4[i4];
        float vv[4] = {v.x, v.y, v.z, v.w};
        int base = i4*4;
        #pragma unroll
        for (int e = 0; e < 4; e++){
            int idx = base + e;
            int c = idx / 192, rem = idx % 192;
            int o = rem / 3, k = rem % 3;
            ksh[k*2048 + c*64 + o] = vv[e];
        }
    }
    __syncthreads();

    // --- dconv phase 1: sc[o][p] for p in [0,256), thread = 4 ch x 8 p ---
    {
        int o0 = (tid >> 5) * 4;
        int p0 = (tid & 31) * 8;
        uint64_t acc[2][8];
        #pragma unroll
        for (int m = 0; m < 2; m++){
            uint64_t bp = pack2f(bias[o0 + 2*m], bias[o0 + 2*m + 1]);
            #pragma unroll
            for (int j = 0; j < 8; j++) acc[m][j] = bp;
        }
        for (int i = 0; i < NCH; i++){
            const float* xr = &sx[i*312 + p0];
            #pragma unroll
            for (int k = 0; k < 3; k++){
                ulonglong2 wp = *(const ulonglong2*)&ws[k*1024 + i*32 + o0];
                #pragma unroll
                for (int j = 0; j < 8; j++){
                    uint64_t xb = bcast2f(xr[j + k*D]);
                    fma2(acc[0][j], wp.x, xb);
                    fma2(acc[1][j], wp.y, xb);
                }
            }
        }
        #pragma unroll
        for (int cc = 0; cc < 4; cc++)
            #pragma unroll
            for (int j = 0; j < 8; j++){
                float2 u = unpack2f(acc[cc>>1][j]);
                sc[(o0 + cc)*264 + p0 + j] = lrelu((cc & 1) ? u.y : u.x);
            }
    }
    // --- dconv phase 2: p = 256, 257 (64 values, scalar, warps 0-1) ---
    if (tid < 64){
        int ch = tid >> 1, p = 256 + (tid & 1);
        float acc = bias[ch];
        for (int i = 0; i < NCH; i++){
            #pragma unroll
            for (int k = 0; k < 3; k++)
                acc += ws[k*1024 + i*32 + ch] * sx[i*312 + p + k*D];
        }
        sc[ch*264 + p] = lrelu(acc);
    }
    __syncthreads();

    // --- LVC + gate + residual: thread = 4 ch x 8 samples ---
    int o0 = (tid >> 5) * 4;
    int s0 = (tid & 31) * 8;
    const float* Bb = &g_BS[(b*256 + layer*64)*L_];
    uint64_t accL[2][8], accH[2][8];
    #pragma unroll
    for (int m = 0; m < 2; m++){
        uint64_t bl = pack2f(Bb[(o0 + 2*m)*L_ + l],      Bb[(o0 + 2*m + 1)*L_ + l]);
        uint64_t bh = pack2f(Bb[(o0 + 2*m + 32)*L_ + l], Bb[(o0 + 2*m + 33)*L_ + l]);
        #pragma unroll
        for (int j = 0; j < 8; j++){ accL[m][j] = bl; accH[m][j] = bh; }
    }
    for (int c = 0; c < NCH; c++){
        const float* xr = &sc[c*264 + s0];
        float4 xa = *(const float4*)xr;
        float4 xbv = *(const float4*)(xr + 4);
        float2 xc = *(const float2*)(xr + 8);
        float xw[10] = {xa.x, xa.y, xa.z, xa.w, xbv.x, xbv.y, xbv.z, xbv.w, xc.x, xc.y};
        #pragma unroll
        for (int k = 0; k < 3; k++){
            ulonglong2 wl = *(const ulonglong2*)&ksh[k*2048 + c*64 + o0];
            ulonglong2 wh = *(const ulonglong2*)&ksh[k*2048 + c*64 + o0 + 32];
            #pragma unroll
            for (int j = 0; j < 8; j++){
                uint64_t x = bcast2f(xw[j + k]);
                fma2(accL[0][j], wl.x, x);
                fma2(accL[1][j], wl.y, x);
                fma2(accH[0][j], wh.x, x);
                fma2(accH[1][j], wh.y, x);
            }
        }
    }
    #pragma unroll
    for (int cc = 0; cc < 4; cc++){
        int oc = o0 + cc;
        const float* Hrow = &Hb[oc*T_FULL + tseg + s0];
        float4 r0 = *(const float4*)Hrow;
        float4 r1 = *(const float4*)(Hrow + 4);
        float rr[8] = {r0.x, r0.y, r0.z, r0.w, r1.x, r1.y, r1.z, r1.w};
        float tmp[8];
        #pragma unroll
        for (int j = 0; j < 8; j++){
            float2 uL = unpack2f(accL[cc>>1][j]);
            float2 uH = unpack2f(accH[cc>>1][j]);
            float aL = (cc & 1) ? uL.y : uL.x;
            float aH = (cc & 1) ? uH.y : uH.x;
            float sg = 1.f / (1.f + __expf(-aL));
            float th = tanhf(aH);
            tmp[j] = sg*th + rr[j];
        }
        float* dst = &Hout[(b*NCH + oc)*T_FULL + tseg + s0];
        *(float4*)dst     = make_float4(tmp[0], tmp[1], tmp[2], tmp[3]);
        *(float4*)(dst+4) = make_float4(tmp[4], tmp[5], tmp[6], tmp[7]);
    }
}

// ============================================================
extern "C" void kernel_launch(void* const* d_in, const int* in_sizes, int n_in,
                              void* d_out, int out_size){
    const float* hidden  = (const float*)d_in[0];
    const float* spec    = (const float*)d_in[1];
    const float* convt_w = (const float*)d_in[2];
    const float* convt_b = (const float*)d_in[3];
    const float* kp_in_w = (const float*)d_in[4];
    const float* kp_in_b = (const float*)d_in[5];
    const float* rb_w1   = (const float*)d_in[6];
    const float* rb_b1   = (const float*)d_in[7];
    const float* rb_w2   = (const float*)d_in[8];
    const float* rb_b2   = (const float*)d_in[9];
    const float* kern_w  = (const float*)d_in[10];
    const float* kern_b  = (const float*)d_in[11];
    const float* bias_w  = (const float*)d_in[12];
    const float* bias_b  = (const float*)d_in[13];
    const float* lvc_w   = (const float*)d_in[14];
    const float* lvc_b   = (const float*)d_in[15];

    cudaFuncSetAttribute(k_pred, cudaFuncAttributeMaxDynamicSharedMemorySize, PRED_SMEM);
    cudaFuncSetAttribute(k_fused<1>,  cudaFuncAttributeMaxDynamicSharedMemorySize, FUSED_SMEM);
    cudaFuncSetAttribute(k_fused<3>,  cudaFuncAttributeMaxDynamicSharedMemorySize, FUSED_SMEM);
    cudaFuncSetAttribute(k_fused<9>,  cudaFuncAttributeMaxDynamicSharedMemorySize, FUSED_SMEM);
    cudaFuncSetAttribute(k_fused<27>, cudaFuncAttributeMaxDynamicSharedMemorySize, FUSED_SMEM);

    // idx 2,3
    k_convT<<<dim3(256, B_), 256>>>(hidden, convt_w, convt_b);
    k_pred<<<dim3(B_, 8), 256, PRED_SMEM>>>(spec, kp_in_w, kp_in_b,
                                            rb_w1, rb_b1, rb_w2, rb_b2);
    // idx 4: GEMM + fused bias conv (grid.x = 192 kern blocks + 2 bias blocks)
    k_kern_gemm<<<dim3(KC_/128 + 2, (B_*L_)/64), 256>>>(kern_w, kern_b, bias_w, bias_b);

    // idx 5..8: four fused dconv+LVC layers (idx 5 gets profiled)
    dim3 dg(L_, B_);
    k_fused<1> <<<dg, 256, FUSED_SMEM>>>(0, lvc_w,        lvc_b,      nullptr);
    k_fused<3> <<<dg, 256, FUSED_SMEM>>>(1, lvc_w + 3072, lvc_b + 32, nullptr);
    k_fused<9> <<<dg, 256, FUSED_SMEM>>>(2, lvc_w + 6144, lvc_b + 64, nullptr);
    k_fused<27><<<dg, 256, FUSED_SMEM>>>(3, lvc_w + 9216, lvc_b + 96, (float*)d_out);
}

// round 13
// speedup vs baseline: 1.1587x; 1.0045x over previous
#include <cuda_runtime.h>
#include <cstdint>
#include <math.h>

#define B_     4
#define NCH    32
#define T_FULL 65536
#define T_IN   8192
#define L_     256
#define HOP_   256
#define H_     64
#define KC_    24576

// ---- scratch (device globals; no allocation allowed) ----
__device__ float g_H [B_*NCH*T_FULL];   // hidden state buffer A
__device__ float g_C [B_*NCH*T_FULL];   // hidden state buffer B (double-buffer)
__device__ float g_F0[B_*H_*L_];
__device__ float g_KT[B_*L_*KC_];       // predicted kernels [n=b*L+l][kc]
__device__ float g_BS[B_*256*L_];       // predicted biases [b][bc][l]

__device__ __forceinline__ float lrelu(float x){ return x >= 0.f ? x : 0.2f*x; }

// ---- packed f32x2 helpers ----
__device__ __forceinline__ uint64_t pack2f(float lo, float hi){
    uint64_t r; asm("mov.b64 %0, {%1, %2};" : "=l"(r) : "f"(lo), "f"(hi)); return r;
}
__device__ __forceinline__ uint64_t bcast2f(float x){ return pack2f(x, x); }
__device__ __forceinline__ void fma2(uint64_t& d, uint64_t a, uint64_t b){
    asm("fma.rn.f32x2 %0, %1, %2, %0;" : "+l"(d) : "l"(a), "l"(b));
}
__device__ __forceinline__ float2 unpack2f(uint64_t v){
    float2 r; asm("mov.b64 {%0, %1}, %2;" : "=f"(r.x), "=f"(r.y) : "l"(v)); return r;
}

// ============================================================
// K1: conv_transpose1d  (stride 8, K=16, pad 4) -> g_H
// ============================================================
__global__ void k_convT(const float* __restrict__ x, const float* __restrict__ w,
                        const float* __restrict__ bias){
    int b  = blockIdx.y;
    int t0 = blockIdx.x * 256;
    int tid = threadIdx.x;
    int r = tid & 7, o = tid >> 3;
    __shared__ float xs[NCH*36];
    const float* xb = x + b*NCH*T_IN;
    int jbase = t0/8 - 1;
    for (int idx = tid; idx < NCH*34; idx += 256){
        int c = idx / 34, p = idx % 34;
        int j = jbase + p;
        xs[c*36 + p] = (j >= 0 && j < T_IN) ? xb[c*T_IN + j] : 0.f;
    }
    __syncthreads();
    float acc[32];
    float bv = bias[o];
    #pragma unroll
    for (int s = 0; s < 32; s++) acc[s] = bv;
    int off = (r + 4) & 7;
    int e   = (off >= 4) ? 1 : 0;
    for (int i = 0; i < NCH; i++){
        float w1 = w[(i*32 + o)*16 + r];
        float w2 = w[(i*32 + o)*16 + r + 8];
        const float* xr = &xs[i*36 + e];
        float vp = xr[0];
        #pragma unroll
        for (int s = 0; s < 32; s++){
            float v = xr[s + 1];
            acc[s] += w1*v + w2*vp;
            vp = v;
        }
    }
    float* out = &g_H[(b*NCH + o)*T_FULL];
    #pragma unroll
    for (int s = 0; s < 32; s++) out[t0 + off + 8*s] = acc[s];
}

// ============================================================
// K2: FUSED kernel predictor (spec conv + 3 residual blocks).
// ============================================================
#define PRED_SMEM ((100*52 + 64*52 + 64*52 + 16000)*4)

__device__ __forceinline__ void pred_conv3(
    const float* src, float* dst, const float* rsd, float* wbuf,
    const float* __restrict__ wsrc, const float* __restrict__ bsrc,
    int plo, int phi, int l0, int hq, int pb, int tid){
    __syncthreads();
    for (int idx = tid; idx < 64*192; idx += 256){
        int h = idx/192, ck = idx%192;
        wbuf[ck*64 + h] = wsrc[h*192 + ck];
    }
    __syncthreads();
    uint64_t acc[2][3];
    #pragma unroll
    for (int m = 0; m < 2; m++){
        uint64_t bp = pack2f(bsrc[hq*4 + 2*m], bsrc[hq*4 + 2*m + 1]);
        acc[m][0]=bp; acc[m][1]=bp; acc[m][2]=bp;
    }
    for (int c = 0; c < 64; c++){
        float xv[5];
        #pragma unroll
        for (int m = 0; m < 5; m++) xv[m] = src[c*52 + pb + 1 + m];
        #pragma unroll
        for (int k = 0; k < 3; k++){
            ulonglong2 wp = *(const ulonglong2*)&wbuf[(c*3 + k)*64 + hq*4];
            #pragma unroll
            for (int j = 0; j < 3; j++){
                uint64_t xb = bcast2f(xv[j + k]);
                fma2(acc[0][j], wp.x, xb);
                fma2(acc[1][j], wp.y, xb);
            }
        }
    }
    #pragma unroll
    for (int m = 0; m < 2; m++)
    #pragma unroll
    for (int j = 0; j < 3; j++){
        int p = pb + j;
        if (p >= plo && p <= phi){
            int gl = l0 - 8 + p;
            bool ok = (gl >= 0 && gl < L_);
            float2 u = unpack2f(acc[m][j]);
            int ch0 = hq*4 + 2*m;
            float v0 = lrelu(u.x), v1 = lrelu(u.y);
            if (rsd){ v0 += rsd[ch0*52 + p + 2]; v1 += rsd[(ch0+1)*52 + p + 2]; }
            dst[ch0*52 + p + 2]     = ok ? v0 : 0.f;
            dst[(ch0+1)*52 + p + 2] = ok ? v1 : 0.f;
        }
    }
}

__global__ void __launch_bounds__(256)
k_pred(const float* __restrict__ spec,
       const float* __restrict__ kp_w, const float* __restrict__ kp_b,
       const float* __restrict__ rb_w1, const float* __restrict__ rb_b1,
       const float* __restrict__ rb_w2, const float* __restrict__ rb_b2){
    extern __shared__ float sm[];
    float* sspec = sm;
    float* bufA  = sm + 100*52;
    float* bufB  = bufA + 64*52;
    float* wbuf  = bufB + 64*52;
    int b = blockIdx.x, ls = blockIdx.y;
    int l0 = ls*32;
    int tid = threadIdx.x;
    int hq = tid >> 4;
    int pb = (tid & 15) * 3;

    const float* sp = spec + b*100*L_;
    for (int idx = tid; idx < 100*52; idx += 256){
        int c = idx/52, q = idx%52;
        int gl = l0 - 10 + q;
        sspec[c*52 + q] = (gl >= 0 && gl < L_) ? sp[c*L_ + gl] : 0.f;
    }
    uint64_t acc[2][3];
    #pragma unroll
    for (int m = 0; m < 2; m++){
        uint64_t bp = pack2f(kp_b[hq*4 + 2*m], kp_b[hq*4 + 2*m + 1]);
        acc[m][0]=bp; acc[m][1]=bp; acc[m][2]=bp;
    }
    for (int chunk = 0; chunk < 2; chunk++){
        __syncthreads();
        for (int idx = tid; idx < 16000; idx += 256){
            int h = idx/250, ck = idx%250;
            wbuf[ck*64 + h] = kp_w[h*500 + chunk*250 + ck];
        }
        __syncthreads();
        for (int c2 = 0; c2 < 50; c2++){
            int c = chunk*50 + c2;
            float xv[7];
            #pragma unroll
            for (int m = 0; m < 7; m++) xv[m] = sspec[c*52 + pb + m];
            #pragma unroll
            for (int k = 0; k < 5; k++){
                ulonglong2 wp = *(const ulonglong2*)&wbuf[(c2*5 + k)*64 + hq*4];
                #pragma unroll
                for (int j = 0; j < 3; j++){
                    uint64_t xb = bcast2f(xv[j + k]);
                    fma2(acc[0][j], wp.x, xb);
                    fma2(acc[1][j], wp.y, xb);
                }
            }
        }
    }
    #pragma unroll
    for (int m = 0; m < 2; m++)
    #pragma unroll
    for (int j = 0; j < 3; j++){
        int p = pb + j;
        if (p >= 2 && p <= 45){
            int gl = l0 - 8 + p;
            bool ok = (gl >= 0 && gl < L_);
            float2 u = unpack2f(acc[m][j]);
            int ch0 = hq*4 + 2*m;
            bufA[ch0*52 + p + 2]     = ok ? u.x : 0.f;
            bufA[(ch0+1)*52 + p + 2] = ok ? u.y : 0.f;
        }
    }
    #pragma unroll 1
    for (int i = 0; i < 3; i++){
        pred_conv3(bufA, bufB, nullptr, wbuf, rb_w1 + i*12288, rb_b1 + i*64,
                   3+2*i, 44-2*i, l0, hq, pb, tid);
        pred_conv3(bufB, bufA, bufA,    wbuf, rb_w2 + i*12288, rb_b2 + i*64,
                   4+2*i, 43-2*i, l0, hq, pb, tid);
    }
    __syncthreads();
    #pragma unroll
    for (int m = 0; m < 2; m++)
    #pragma unroll
    for (int j = 0; j < 3; j++){
        int p = pb + j;
        if (p >= 8 && p <= 39){
            int l = l0 - 8 + p;
            int ch0 = hq*4 + 2*m;
            g_F0[(b*H_ + ch0    )*L_ + l] = bufA[ch0*52 + p + 2];
            g_F0[(b*H_ + ch0 + 1)*L_ + l] = bufA[(ch0+1)*52 + p + 2];
        }
    }
}

// ============================================================
// K5: kern conv GEMM (f32x2), tile 128(kc) x 64(n), DOUBLE-
// BUFFERED smem staging (one __syncthreads per BK step).
// 2 tail block-rows compute the bias conv into g_BS.
// ============================================================
__global__ void __launch_bounds__(256)
k_kern_gemm(const float* __restrict__ A, const float* __restrict__ Ab,
            const float* __restrict__ Bw, const float* __restrict__ Bb){
    int kc0 = blockIdx.x * 128;
    bool is_bias = (kc0 >= KC_);
    int n0  = blockIdx.y * 64;
    int b   = n0 / L_;
    int l0w = n0 % L_;
    int tid = threadIdx.x;
    int warp = tid >> 5, lane = tid & 31;
    int ty = (warp << 1) | (lane >> 4);
    int tx = lane & 15;
    __shared__ __align__(16) float As[2][16][128];
    __shared__ __align__(16) float Xs[2][16][68];
    const float* F = &g_F0[b*H_*L_];
    const float* Arow_base = is_bias ? Bw : A;
    const float* bias_base = is_bias ? Bb : Ab;
    int row_off = is_bias ? (kc0 - KC_) : kc0;

    uint64_t acc[4][4];
    #pragma unroll
    for (int m = 0; m < 4; m++){
        uint64_t bp = pack2f(bias_base[row_off + ty*8 + 2*m],
                             bias_base[row_off + ty*8 + 2*m + 1]);
        #pragma unroll
        for (int j = 0; j < 4; j++) acc[m][j] = bp;
    }
    int arow = tid >> 1, ac0 = (tid & 1) * 8;
    int xrr = tid >> 4, xc0 = (tid & 15) * 4;
    const float* Aptr = &Arow_base[(row_off + arow)*192 + ac0];

    // prologue: stage bk=0 into buffer 0
    {
        float4 v0 = *(const float4*)(Aptr);
        float4 v1 = *(const float4*)(Aptr + 4);
        As[0][ac0+0][arow] = v0.x; As[0][ac0+1][arow] = v0.y;
        As[0][ac0+2][arow] = v0.z; As[0][ac0+3][arow] = v0.w;
        As[0][ac0+4][arow] = v1.x; As[0][ac0+5][arow] = v1.y;
        As[0][ac0+6][arow] = v1.z; As[0][ac0+7][arow] = v1.w;
        int hh = xrr/3, k = xrr%3;
        #pragma unroll
        for (int q = 0; q < 4; q++){
            int t = l0w + xc0 + q + k - 1;
            Xs[0][xrr][xc0+q] = (t >= 0 && t < L_) ? F[hh*L_ + t] : 0.f;
        }
    }
    __syncthreads();

    #pragma unroll 1
    for (int bk = 0; bk < 12; bk++){
        int cur = bk & 1, nxt = cur ^ 1;
        if (bk < 11){
            int r0 = (bk + 1)*16;
            float4 v0 = *(const float4*)(Aptr + r0);
            float4 v1 = *(const float4*)(Aptr + r0 + 4);
            As[nxt][ac0+0][arow] = v0.x; As[nxt][ac0+1][arow] = v0.y;
            As[nxt][ac0+2][arow] = v0.z; As[nxt][ac0+3][arow] = v0.w;
            As[nxt][ac0+4][arow] = v1.x; As[nxt][ac0+5][arow] = v1.y;
            As[nxt][ac0+6][arow] = v1.z; As[nxt][ac0+7][arow] = v1.w;
            int r = r0 + xrr;
            int hh = r/3, k = r%3;
            #pragma unroll
            for (int q = 0; q < 4; q++){
                int t = l0w + xc0 + q + k - 1;
                Xs[nxt][xrr][xc0+q] = (t >= 0 && t < L_) ? F[hh*L_ + t] : 0.f;
            }
        }
        #pragma unroll
        for (int kk = 0; kk < 16; kk++){
            ulonglong2 aA = *(const ulonglong2*)&As[cur][kk][ty*8];
            ulonglong2 aB = *(const ulonglong2*)&As[cur][kk][ty*8 + 4];
            uint64_t a2[4] = {aA.x, aA.y, aB.x, aB.y};
            float4 xv = *(const float4*)&Xs[cur][kk][tx*4];
            uint64_t xb[4] = {bcast2f(xv.x), bcast2f(xv.y), bcast2f(xv.z), bcast2f(xv.w)};
            #pragma unroll
            for (int j = 0; j < 4; j++)
                #pragma unroll
                for (int m = 0; m < 4; m++)
                    fma2(acc[m][j], a2[m], xb[j]);
        }
        __syncthreads();
    }
    if (!is_bias){
        #pragma unroll
        for (int j = 0; j < 4; j++){
            int n = n0 + tx*4 + j;
            #pragma unroll
            for (int m = 0; m < 4; m++){
                float2 p = unpack2f(acc[m][j]);
                *(float2*)&g_KT[n*KC_ + kc0 + ty*8 + 2*m] = p;
            }
        }
    } else {
        #pragma unroll
        for (int j = 0; j < 4; j++){
            int l = l0w + tx*4 + j;
            #pragma unroll
            for (int m = 0; m < 4; m++){
                float2 p = unpack2f(acc[m][j]);
                int bc = row_off + ty*8 + 2*m;
                g_BS[(b*256 + bc    )*L_ + l] = p.x;
                g_BS[(b*256 + bc + 1)*L_ + l] = p.y;
            }
        }
    }
}

// ============================================================
// K7+K8 FUSED: lrelu -> dilated conv -> lrelu (into smem sc)
// -> location-variable conv + bias + gating + residual.
// sc boundary samples (t=-1 at l=0, t=T at l=255) forced to 0
// to match the reference's zero-padded LVC input.
// ============================================================
#define FUSED_SMEM ((32*312 + 3072 + 32*264 + 6144)*4)
template<int D>
__global__ void __launch_bounds__(256)
k_fused(int layer, const float* __restrict__ w, const float* __restrict__ bias,
        float* __restrict__ outp){
    extern __shared__ float sm[];
    float* sx  = sm;                    // 32 x 312: lrelu(Hin) window
    float* ws  = sm + 32*312;           // [k][i][o] 3072
    float* sc  = ws + 3072;             // 32 x 264 (258 used): conv out
    float* ksh = sc + 32*264;           // [k][c][o] 6144
    int b = blockIdx.y, l = blockIdx.x;
    int tid = threadIdx.x;
    int tseg = l*HOP_;
    const float* Hin  = (layer & 1) ? g_C : g_H;
    float* Hout = outp ? outp : ((layer & 1) ? g_H : g_C);
    const float* Hb = &Hin[b*NCH*T_FULL];

    const int W2 = 258 + 2*D;
    for (int idx = tid; idx < NCH*W2; idx += 256){
        int c = idx / W2, q = idx % W2;
        int t = tseg - 1 - D + q;
        sx[c*312 + q] = (t >= 0 && t < T_FULL) ? lrelu(Hb[c*T_FULL + t]) : 0.f;
    }
    for (int idx = tid; idx < 3072; idx += 256){
        int o = idx / 96, rem = idx % 96;
        int i = rem / 3, k = rem % 3;
        ws[k*1024 + i*32 + o] = w[idx];
    }
    const float* KTb = &g_KT[(b*L_ + l)*KC_ + layer*6144];
    const float4* K4 = (const float4*)KTb;
    for (int i4 = tid; i4 < 1536; i4 += 256){
        float4 v = K4[i4];
        float vv[4] = {v.x, v.y, v.z, v.w};
        int base = i4*4;
        #pragma unroll
        for (int e = 0; e < 4; e++){
            int idx = base + e;
            int c = idx / 192, rem = idx % 192;
            int o = rem / 3, k = rem % 3;
            ksh[k*2048 + c*64 + o] = vv[e];
        }
    }
    __syncthreads();

    // --- dconv phase 1: sc[o][p] for p in [0,256), thread = 4 ch x 8 p ---
    {
        int o0 = (tid >> 5) * 4;
        int p0 = (tid & 31) * 8;
        uint64_t acc[2][8];
        #pragma unroll
        for (int m = 0; m < 2; m++){
            uint64_t bp = pack2f(bias[o0 + 2*m], bias[o0 + 2*m + 1]);
            #pragma unroll
            for (int j = 0; j < 8; j++) acc[m][j] = bp;
        }
        for (int i = 0; i < NCH; i++){
            const float* xr = &sx[i*312 + p0];
            #pragma unroll
            for (int k = 0; k < 3; k++){
                ulonglong2 wp = *(const ulonglong2*)&ws[k*1024 + i*32 + o0];
                #pragma unroll
                for (int j = 0; j < 8; j++){
                    uint64_t xb = bcast2f(xr[j + k*D]);
                    fma2(acc[0][j], wp.x, xb);
                    fma2(acc[1][j], wp.y, xb);
                }
            }
        }
        #pragma unroll
        for (int cc = 0; cc < 4; cc++)
            #pragma unroll
            for (int j = 0; j < 8; j++){
                float2 u = unpack2f(acc[cc>>1][j]);
                float v = lrelu((cc & 1) ? u.y : u.x);
                if (l == 0 && p0 + j == 0) v = 0.f;   // LVC zero-pad at t=-1
                sc[(o0 + cc)*264 + p0 + j] = v;
            }
    }
    // --- dconv phase 2: p = 256, 257 (64 values, scalar, warps 0-1) ---
    if (tid < 64){
        int ch = tid >> 1, p = 256 + (tid & 1);
        float acc = bias[ch];
        for (int i = 0; i < NCH; i++){
            #pragma unroll
            for (int k = 0; k < 3; k++)
                acc += ws[k*1024 + i*32 + ch] * sx[i*312 + p + k*D];
        }
        float v = lrelu(acc);
        if (l == L_ - 1 && p == 257) v = 0.f;         // LVC zero-pad at t=T
        sc[ch*264 + p] = v;
    }
    __syncthreads();

    // --- LVC + gate + residual: thread = 4 ch x 8 samples ---
    int o0 = (tid >> 5) * 4;
    int s0 = (tid & 31) * 8;
    const float* Bb = &g_BS[(b*256 + layer*64)*L_];
    uint64_t accL[2][8], accH[2][8];
    #pragma unroll
    for (int m = 0; m < 2; m++){
        uint64_t bl = pack2f(Bb[(o0 + 2*m)*L_ + l],      Bb[(o0 + 2*m + 1)*L_ + l]);
        uint64_t bh = pack2f(Bb[(o0 + 2*m + 32)*L_ + l], Bb[(o0 + 2*m + 33)*L_ + l]);
        #pragma unroll
        for (int j = 0; j < 8; j++){ accL[m][j] = bl; accH[m][j] = bh; }
    }
    for (int c = 0; c < NCH; c++){
        const float* xr = &sc[c*264 + s0];
        float4 xa = *(const float4*)xr;
        float4 xbv = *(const float4*)(xr + 4);
        float2 xc = *(const float2*)(xr + 8);
        float xw[10] = {xa.x, xa.y, xa.z, xa.w, xbv.x, xbv.y, xbv.z, xbv.w, xc.x, xc.y};
        #pragma unroll
        for (int k = 0; k < 3; k++){
            ulonglong2 wl = *(const ulonglong2*)&ksh[k*2048 + c*64 + o0];
            ulonglong2 wh = *(const ulonglong2*)&ksh[k*2048 + c*64 + o0 + 32];
            #pragma unroll
            for (int j = 0; j < 8; j++){
                uint64_t x = bcast2f(xw[j + k]);
                fma2(accL[0][j], wl.x, x);
                fma2(accL[1][j], wl.y, x);
                fma2(accH[0][j], wh.x, x);
                fma2(accH[1][j], wh.y, x);
            }
        }
    }
    #pragma unroll
    for (int cc = 0; cc < 4; cc++){
        int oc = o0 + cc;
        const float* Hrow = &Hb[oc*T_FULL + tseg + s0];
        float4 r0 = *(const float4*)Hrow;
        float4 r1 = *(const float4*)(Hrow + 4);
        float rr[8] = {r0.x, r0.y, r0.z, r0.w, r1.x, r1.y, r1.z, r1.w};
        float tmp[8];
        #pragma unroll
        for (int j = 0; j < 8; j++){
            float2 uL = unpack2f(accL[cc>>1][j]);
            float2 uH = unpack2f(accH[cc>>1][j]);
            float aL = (cc & 1) ? uL.y : uL.x;
            float aH = (cc & 1) ? uH.y : uH.x;
            float sg = 1.f / (1.f + __expf(-aL));
            float th = tanhf(aH);
            tmp[j] = sg*th + rr[j];
        }
        float* dst = &Hout[(b*NCH + oc)*T_FULL + tseg + s0];
        *(float4*)dst     = make_float4(tmp[0], tmp[1], tmp[2], tmp[3]);
        *(float4*)(dst+4) = make_float4(tmp[4], tmp[5], tmp[6], tmp[7]);
    }
}

// ============================================================
extern "C" void kernel_launch(void* const* d_in, const int* in_sizes, int n_in,
                              void* d_out, int out_size){
    const float* hidden  = (const float*)d_in[0];
    const float* spec    = (const float*)d_in[1];
    const float* convt_w = (const float*)d_in[2];
    const float* convt_b = (const float*)d_in[3];
    const float* kp_in_w = (const float*)d_in[4];
    const float* kp_in_b = (const float*)d_in[5];
    const float* rb_w1   = (const float*)d_in[6];
    const float* rb_b1   = (const float*)d_in[7];
    const float* rb_w2   = (const float*)d_in[8];
    const float* rb_b2   = (const float*)d_in[9];
    const float* kern_w  = (const float*)d_in[10];
    const float* kern_b  = (const float*)d_in[11];
    const float* bias_w  = (const float*)d_in[12];
    const float* bias_b  = (const float*)d_in[13];
    const float* lvc_w   = (const float*)d_in[14];
    const float* lvc_b   = (const float*)d_in[15];

    cudaFuncSetAttribute(k_pred, cudaFuncAttributeMaxDynamicSharedMemorySize, PRED_SMEM);
    cudaFuncSetAttribute(k_fused<1>,  cudaFuncAttributeMaxDynamicSharedMemorySize, FUSED_SMEM);
    cudaFuncSetAttribute(k_fused<3>,  cudaFuncAttributeMaxDynamicSharedMemorySize, FUSED_SMEM);
    cudaFuncSetAttribute(k_fused<9>,  cudaFuncAttributeMaxDynamicSharedMemorySize, FUSED_SMEM);
    cudaFuncSetAttribute(k_fused<27>, cudaFuncAttributeMaxDynamicSharedMemorySize, FUSED_SMEM);

    k_convT<<<dim3(256, B_), 256>>>(hidden, convt_w, convt_b);
    k_pred<<<dim3(B_, 8), 256, PRED_SMEM>>>(spec, kp_in_w, kp_in_b,
                                            rb_w1, rb_b1, rb_w2, rb_b2);
    // GEMM + fused bias conv
    k_kern_gemm<<<dim3(KC_/128 + 2, (B_*L_)/64), 256>>>(kern_w, kern_b, bias_w, bias_b);

    // four fused dconv+LVC layers (first one lands at ncu position)
    dim3 dg(L_, B_);
    k_fused<1> <<<dg, 256, FUSED_SMEM>>>(0, lvc_w,        lvc_b,      nullptr);
    k_fused<3> <<<dg, 256, FUSED_SMEM>>>(1, lvc_w + 3072, lvc_b + 32, nullptr);
    k_fused<9> <<<dg, 256, FUSED_SMEM>>>(2, lvc_w + 6144, lvc_b + 64, nullptr);
    k_fused<27><<<dg, 256, FUSED_SMEM>>>(3, lvc_w + 9216, lvc_b + 96, (float*)d_out);
}